// round 1
// baseline (speedup 1.0000x reference)
#include <cuda_runtime.h>
#include <mma.h>
using namespace nvcuda;

#define T_TOK 2048
#define H_DIM 2048
#define F_DIM 1408
#define SF_DIM 2816
#define N_EXP 8

#define BM 64
#define BN 128
#define BK 32
#define LDA 36    // BK + 4 pad
#define LDB 132   // BN + 4 pad
#define LDC 68    // 64 + 4 pad (epilogue staging)

// ---- scratch (device globals: no allocations allowed) ----
__device__ int   g_count[N_EXP];
__device__ int   g_perm[N_EXP * T_TOK];
__device__ float g_wgt [N_EXP * T_TOK];
__device__ float g_act [(size_t)N_EXP * T_TOK * F_DIM];   // routed act (slot-indexed per expert)
__device__ float g_sact[(size_t)T_TOK * SF_DIM];          // shared-expert act

// ---------------------------------------------------------------------------
__global__ void zero_counts_kernel() {
    if (threadIdx.x < N_EXP) g_count[threadIdx.x] = 0;
}

// ---------------------------------------------------------------------------
// Gating: softmax(x @ gw^T) rows, top-2, build per-expert token lists.
__global__ void gate_topk_kernel(const float* __restrict__ x,
                                 const float* __restrict__ gw) {
    __shared__ float xs[H_DIM];
    __shared__ float logits[N_EXP];
    int t = blockIdx.x;
    const float4* xr = (const float4*)(x + (size_t)t * H_DIM);
    for (int i = threadIdx.x; i < H_DIM / 4; i += blockDim.x)
        ((float4*)xs)[i] = xr[i];
    __syncthreads();

    int w = threadIdx.x >> 5, lane = threadIdx.x & 31;
    if (w < N_EXP) {
        const float* gr = gw + (size_t)w * H_DIM;
        float s = 0.f;
        for (int i = lane; i < H_DIM; i += 32) s += xs[i] * gr[i];
        #pragma unroll
        for (int o = 16; o; o >>= 1) s += __shfl_xor_sync(0xffffffffu, s, o);
        if (lane == 0) logits[w] = s;
    }
    __syncthreads();

    if (threadIdx.x == 0) {
        float m = logits[0];
        #pragma unroll
        for (int e = 1; e < N_EXP; e++) m = fmaxf(m, logits[e]);
        float p[N_EXP]; float sum = 0.f;
        #pragma unroll
        for (int e = 0; e < N_EXP; e++) { p[e] = expf(logits[e] - m); sum += p[e]; }
        float inv = 1.f / sum;
        int i0 = 0;
        #pragma unroll
        for (int e = 1; e < N_EXP; e++) if (p[e] > p[i0]) i0 = e;
        int i1 = (i0 == 0) ? 1 : 0;
        #pragma unroll
        for (int e = 0; e < N_EXP; e++) if (e != i0 && p[e] > p[i1]) i1 = e;

        int s0 = atomicAdd(&g_count[i0], 1);
        g_perm[i0 * T_TOK + s0] = t;
        g_wgt [i0 * T_TOK + s0] = p[i0] * inv;
        int s1 = atomicAdd(&g_count[i1], 1);
        g_perm[i1 * T_TOK + s1] = t;
        g_wgt [i1 * T_TOK + s1] = p[i1] * inv;
    }
}

// ---------------------------------------------------------------------------
// Fused gate/up GEMM:  act = silu(A @ W1) * (A @ W2)
// ROUTED: A rows gathered via g_perm for expert blockIdx.z, out = g_act[e], N=F_DIM
// !ROUTED: A = x directly, out = g_sact, N=SF_DIM
template <bool ROUTED>
__global__ void __launch_bounds__(256)
act_kernel(const float* __restrict__ x,
           const float* __restrict__ W1base,
           const float* __restrict__ W2base,
           float* __restrict__ outBase,
           int nld) {
    int e = ROUTED ? blockIdx.z : 0;
    int cnt = ROUTED ? g_count[e] : T_TOK;
    int m0 = blockIdx.y * BM;
    if (m0 >= cnt) return;
    int n0 = blockIdx.x * BN;

    __shared__ float sA[BM * LDA];
    __shared__ float sB1[BK * LDB];
    __shared__ float sB2[BK * LDB];
    __shared__ int stok[BM];

    int tid = threadIdx.x;
    if (tid < BM) {
        int slot = m0 + tid;
        stok[tid] = ROUTED ? ((slot < cnt) ? g_perm[e * T_TOK + slot] : 0) : slot;
    }
    __syncthreads();

    const float* W1 = W1base + (ROUTED ? (size_t)e * H_DIM * nld : 0);
    const float* W2 = W2base + (ROUTED ? (size_t)e * H_DIM * nld : 0);
    float* outE = outBase + (ROUTED ? (size_t)e * T_TOK * nld : 0);

    int warp = tid >> 5;
    int wr = warp & 3;   // 4 row groups of 16
    int wc = warp >> 2;  // 2 col groups of 64

    wmma::fragment<wmma::accumulator, 16, 16, 8, float> acc1[4], acc2[4];
    #pragma unroll
    for (int j = 0; j < 4; j++) { wmma::fill_fragment(acc1[j], 0.f); wmma::fill_fragment(acc2[j], 0.f); }

    for (int k0 = 0; k0 < H_DIM; k0 += BK) {
        #pragma unroll
        for (int i = 0; i < 2; i++) {  // A: 64x32 = 512 float4
            int id = tid + i * 256;
            int r = id >> 3, c4 = id & 7;
            *(float4*)(sA + r * LDA + c4 * 4) =
                *(const float4*)(x + (size_t)stok[r] * H_DIM + k0 + c4 * 4);
        }
        #pragma unroll
        for (int i = 0; i < 4; i++) {  // each B: 32x128 = 1024 float4
            int id = tid + i * 256;
            int r = id >> 5, c4 = id & 31;
            size_t gb = (size_t)(k0 + r) * nld + n0 + c4 * 4;
            *(float4*)(sB1 + r * LDB + c4 * 4) = *(const float4*)(W1 + gb);
            *(float4*)(sB2 + r * LDB + c4 * 4) = *(const float4*)(W2 + gb);
        }
        __syncthreads();

        #pragma unroll
        for (int kk = 0; kk < BK; kk += 8) {
            wmma::fragment<wmma::matrix_a, 16, 16, 8, wmma::precision::tf32, wmma::row_major> a;
            wmma::load_matrix_sync(a, sA + (wr * 16) * LDA + kk, LDA);
            #pragma unroll
            for (int i = 0; i < a.num_elements; i++) a.x[i] = wmma::__float_to_tf32(a.x[i]);
            #pragma unroll
            for (int j = 0; j < 4; j++) {
                wmma::fragment<wmma::matrix_b, 16, 16, 8, wmma::precision::tf32, wmma::row_major> b;
                wmma::load_matrix_sync(b, sB1 + kk * LDB + wc * 64 + j * 16, LDB);
                #pragma unroll
                for (int i = 0; i < b.num_elements; i++) b.x[i] = wmma::__float_to_tf32(b.x[i]);
                wmma::mma_sync(acc1[j], a, b, acc1[j]);
                wmma::load_matrix_sync(b, sB2 + kk * LDB + wc * 64 + j * 16, LDB);
                #pragma unroll
                for (int i = 0; i < b.num_elements; i++) b.x[i] = wmma::__float_to_tf32(b.x[i]);
                wmma::mma_sync(acc2[j], a, b, acc2[j]);
            }
        }
        __syncthreads();
    }

    // epilogue: silu(g) * u   (fragments share element->(m,n) mapping)
    #pragma unroll
    for (int j = 0; j < 4; j++) {
        #pragma unroll
        for (int i = 0; i < acc1[j].num_elements; i++) {
            float g = acc1[j].x[i], u = acc2[j].x[i];
            acc1[j].x[i] = (g / (1.f + __expf(-g))) * u;
        }
        wmma::store_matrix_sync(outE + (size_t)(m0 + wr * 16) * nld + n0 + wc * 64 + j * 16,
                                acc1[j], nld, wmma::mem_row_major);
    }
}

// ---------------------------------------------------------------------------
// Down GEMM: C = act @ Wdown.
// ROUTED: per-expert, scatter-add w[slot]*C into out[token,:] with atomics.
// !ROUTED: plain store (runs first, initializes out).
template <bool ROUTED, int KDIM>
__global__ void __launch_bounds__(256)
down_kernel(const float* __restrict__ Abase,
            const float* __restrict__ Bbase,
            float* __restrict__ out) {
    int e = ROUTED ? blockIdx.z : 0;
    int cnt = ROUTED ? g_count[e] : T_TOK;
    int m0 = blockIdx.y * BM;
    if (m0 >= cnt) return;
    int n0 = blockIdx.x * BN;

    __shared__ float smem[BM * LDA + BK * LDB];  // 6528 floats; reused as 64xLDC staging
    __shared__ int stok[BM];
    __shared__ float sw[BM];
    float* sA = smem;
    float* sB = smem + BM * LDA;

    int tid = threadIdx.x;
    if (ROUTED && tid < BM) {
        int slot = m0 + tid;
        bool v = slot < cnt;
        stok[tid] = v ? g_perm[e * T_TOK + slot] : -1;
        sw[tid]   = v ? g_wgt [e * T_TOK + slot] : 0.f;
    }

    const float* A = Abase + (ROUTED ? (size_t)e * T_TOK * KDIM : 0);
    const float* B = Bbase + (ROUTED ? (size_t)e * KDIM * H_DIM : 0);

    int warp = tid >> 5;
    int wr = warp & 3;
    int wc = warp >> 2;

    wmma::fragment<wmma::accumulator, 16, 16, 8, float> acc[4];
    #pragma unroll
    for (int j = 0; j < 4; j++) wmma::fill_fragment(acc[j], 0.f);

    for (int k0 = 0; k0 < KDIM; k0 += BK) {
        #pragma unroll
        for (int i = 0; i < 2; i++) {
            int id = tid + i * 256;
            int r = id >> 3, c4 = id & 7;
            *(float4*)(sA + r * LDA + c4 * 4) =
                *(const float4*)(A + (size_t)(m0 + r) * KDIM + k0 + c4 * 4);
        }
        #pragma unroll
        for (int i = 0; i < 4; i++) {
            int id = tid + i * 256;
            int r = id >> 5, c4 = id & 31;
            *(float4*)(sB + r * LDB + c4 * 4) =
                *(const float4*)(B + (size_t)(k0 + r) * H_DIM + n0 + c4 * 4);
        }
        __syncthreads();

        #pragma unroll
        for (int kk = 0; kk < BK; kk += 8) {
            wmma::fragment<wmma::matrix_a, 16, 16, 8, wmma::precision::tf32, wmma::row_major> a;
            wmma::load_matrix_sync(a, sA + (wr * 16) * LDA + kk, LDA);
            #pragma unroll
            for (int i = 0; i < a.num_elements; i++) a.x[i] = wmma::__float_to_tf32(a.x[i]);
            #pragma unroll
            for (int j = 0; j < 4; j++) {
                wmma::fragment<wmma::matrix_b, 16, 16, 8, wmma::precision::tf32, wmma::row_major> b;
                wmma::load_matrix_sync(b, sB + kk * LDB + wc * 64 + j * 16, LDB);
                #pragma unroll
                for (int i = 0; i < b.num_elements; i++) b.x[i] = wmma::__float_to_tf32(b.x[i]);
                wmma::mma_sync(acc[j], a, b, acc[j]);
            }
        }
        __syncthreads();
    }

    // epilogue: stage each 64-col half in smem, drain with all 256 threads
    float* sC = smem;  // 64 * LDC = 4352 floats <= 6528
    #pragma unroll
    for (int half = 0; half < 2; half++) {
        __syncthreads();
        if (wc == half) {
            #pragma unroll
            for (int j = 0; j < 4; j++)
                wmma::store_matrix_sync(sC + (wr * 16) * LDC + j * 16, acc[j], LDC,
                                        wmma::mem_row_major);
        }
        __syncthreads();
        for (int i = tid; i < BM * 64; i += 256) {
            int r = i >> 6, c = i & 63;
            float v = sC[r * LDC + c];
            if (ROUTED) {
                int tok = stok[r];
                if (tok >= 0)
                    atomicAdd(out + (size_t)tok * H_DIM + n0 + half * 64 + c, sw[r] * v);
            } else {
                out[(size_t)(m0 + r) * H_DIM + n0 + half * 64 + c] = v;
            }
        }
    }
}

// ---------------------------------------------------------------------------
extern "C" void kernel_launch(void* const* d_in, const int* in_sizes, int n_in,
                              void* d_out, int out_size) {
    const float* x  = (const float*)d_in[0];
    const float* gw = (const float*)d_in[1];
    const float* gp = (const float*)d_in[2];
    const float* up = (const float*)d_in[3];
    const float* dp = (const float*)d_in[4];
    const float* sg = (const float*)d_in[5];
    const float* su = (const float*)d_in[6];
    const float* sd = (const float*)d_in[7];
    float* out = (float*)d_out;

    float* actPtr;  cudaGetSymbolAddress((void**)&actPtr,  g_act);
    float* sactPtr; cudaGetSymbolAddress((void**)&sactPtr, g_sact);

    zero_counts_kernel<<<1, 32>>>();
    gate_topk_kernel<<<T_TOK, 256>>>(x, gw);

    // routed fused gate/up -> g_act
    act_kernel<true><<<dim3(F_DIM / BN, T_TOK / BM, N_EXP), 256>>>(x, gp, up, actPtr, F_DIM);
    // shared fused gate/up -> g_sact
    act_kernel<false><<<dim3(SF_DIM / BN, T_TOK / BM, 1), 256>>>(x, sg, su, sactPtr, SF_DIM);

    // shared down: writes (initializes) out
    down_kernel<false, SF_DIM><<<dim3(H_DIM / BN, T_TOK / BM, 1), 256>>>(sactPtr, sd, out);
    // routed down: atomic scatter-add of weighted expert outputs
    down_kernel<true, F_DIM><<<dim3(H_DIM / BN, T_TOK / BM, N_EXP), 256>>>(actPtr, dp, out);
}

// round 2
// speedup vs baseline: 1.6166x; 1.6166x over previous
#include <cuda_runtime.h>
#include <mma.h>
using namespace nvcuda;

#define T_TOK 2048
#define H_DIM 2048
#define F_DIM 1408
#define SF_DIM 2816
#define N_EXP 8

#define BM 64
#define BN 128
#define BK 32
#define LDA 36    // BK + 4 pad   (144B row, 16B aligned)
#define LDB 132   // BN + 4 pad   (528B row, 16B aligned)

// ---- scratch (device globals: no allocations allowed) ----
__device__ int   g_count[N_EXP];
__device__ int   g_perm[N_EXP * T_TOK];
__device__ float g_wgt [N_EXP * T_TOK];
__device__ float g_act [(size_t)N_EXP * T_TOK * F_DIM];
__device__ float g_sact[(size_t)T_TOK * SF_DIM];

__device__ __forceinline__ void cpa16(void* s, const void* g) {
    unsigned sa = (unsigned)__cvta_generic_to_shared(s);
    asm volatile("cp.async.cg.shared.global [%0], [%1], 16;\n" :: "r"(sa), "l"(g));
}
#define CP_COMMIT asm volatile("cp.async.commit_group;\n" ::: "memory")
#define CP_WAIT1  asm volatile("cp.async.wait_group 1;\n" ::: "memory")
#define CP_WAIT0  asm volatile("cp.async.wait_group 0;\n" ::: "memory")

// ---------------------------------------------------------------------------
__global__ void zero_counts_kernel() {
    if (threadIdx.x < N_EXP) g_count[threadIdx.x] = 0;
}

// ---------------------------------------------------------------------------
__global__ void gate_topk_kernel(const float* __restrict__ x,
                                 const float* __restrict__ gw) {
    __shared__ float xs[H_DIM];
    __shared__ float logits[N_EXP];
    int t = blockIdx.x;
    const float4* xr = (const float4*)(x + (size_t)t * H_DIM);
    for (int i = threadIdx.x; i < H_DIM / 4; i += blockDim.x)
        ((float4*)xs)[i] = xr[i];
    __syncthreads();

    int w = threadIdx.x >> 5, lane = threadIdx.x & 31;
    if (w < N_EXP) {
        const float* gr = gw + (size_t)w * H_DIM;
        float s = 0.f;
        for (int i = lane; i < H_DIM; i += 32) s += xs[i] * gr[i];
        #pragma unroll
        for (int o = 16; o; o >>= 1) s += __shfl_xor_sync(0xffffffffu, s, o);
        if (lane == 0) logits[w] = s;
    }
    __syncthreads();

    if (threadIdx.x == 0) {
        float m = logits[0];
        #pragma unroll
        for (int e = 1; e < N_EXP; e++) m = fmaxf(m, logits[e]);
        float p[N_EXP]; float sum = 0.f;
        #pragma unroll
        for (int e = 0; e < N_EXP; e++) { p[e] = expf(logits[e] - m); sum += p[e]; }
        float inv = 1.f / sum;
        int i0 = 0;
        #pragma unroll
        for (int e = 1; e < N_EXP; e++) if (p[e] > p[i0]) i0 = e;
        int i1 = (i0 == 0) ? 1 : 0;
        #pragma unroll
        for (int e = 0; e < N_EXP; e++) if (e != i0 && p[e] > p[i1]) i1 = e;

        int s0 = atomicAdd(&g_count[i0], 1);
        g_perm[i0 * T_TOK + s0] = t;
        g_wgt [i0 * T_TOK + s0] = p[i0] * inv;
        int s1 = atomicAdd(&g_count[i1], 1);
        g_perm[i1 * T_TOK + s1] = t;
        g_wgt [i1 * T_TOK + s1] = p[i1] * inv;
    }
}

// ---------------------------------------------------------------------------
// Fused gate/up GEMM:  act = silu(A @ W1) * (A @ W2)
// dyn smem: sA[2][BM*LDA], sB1[2][BK*LDB], sB2[2][BK*LDB]
template <bool ROUTED>
__global__ void __launch_bounds__(256)
act_kernel(const float* __restrict__ x,
           const float* __restrict__ W1base,
           const float* __restrict__ W2base,
           float* __restrict__ outBase,
           int nld) {
    extern __shared__ float smem[];
    float* sA  = smem;                      // 2 * BM*LDA
    float* sB1 = smem + 2 * BM * LDA;       // 2 * BK*LDB
    float* sB2 = sB1 + 2 * BK * LDB;        // 2 * BK*LDB
    __shared__ int stok[BM];

    int e = ROUTED ? blockIdx.z : 0;
    int cnt = ROUTED ? g_count[e] : T_TOK;
    int m0 = blockIdx.y * BM;
    if (m0 >= cnt) return;
    int n0 = blockIdx.x * BN;
    int tid = threadIdx.x;

    if (tid < BM) {
        int slot = m0 + tid;
        stok[tid] = ROUTED ? ((slot < cnt) ? g_perm[e * T_TOK + slot]
                                           : g_perm[e * T_TOK]) : slot;
    }
    __syncthreads();

    const float* W1 = W1base + (ROUTED ? (size_t)e * H_DIM * nld : 0);
    const float* W2 = W2base + (ROUTED ? (size_t)e * H_DIM * nld : 0);
    float* outE = outBase + (ROUTED ? (size_t)e * T_TOK * nld : 0);

    int warp = tid >> 5;
    int wr = warp & 1;    // 2 row groups of 32
    int wc = warp >> 1;   // 4 col groups of 32

    wmma::fragment<wmma::accumulator, 16, 16, 8, float> acc1[2][2], acc2[2][2];
    #pragma unroll
    for (int i = 0; i < 2; i++)
        #pragma unroll
        for (int j = 0; j < 2; j++) {
            wmma::fill_fragment(acc1[i][j], 0.f);
            wmma::fill_fragment(acc2[i][j], 0.f);
        }

    // stage loaders
    int rA = tid >> 3, cA4 = (tid & 7) * 4;                 // + i*256 rows
    int rB = tid >> 5, cB4 = (tid & 31) * 4;

    #define ACT_LOAD(st, k0)                                                     \
    {                                                                            \
        _Pragma("unroll")                                                        \
        for (int i = 0; i < 2; i++) {                                            \
            int r = rA + i * 32;                                                 \
            cpa16(sA + (st) * BM * LDA + r * LDA + cA4,                          \
                  x + (size_t)stok[r] * H_DIM + (k0) + cA4);                     \
        }                                                                        \
        _Pragma("unroll")                                                        \
        for (int i = 0; i < 4; i++) {                                            \
            int r = rB + i * 8;                                                  \
            size_t gb = (size_t)((k0) + r) * nld + n0 + cB4;                     \
            cpa16(sB1 + (st) * BK * LDB + r * LDB + cB4, W1 + gb);               \
            cpa16(sB2 + (st) * BK * LDB + r * LDB + cB4, W2 + gb);               \
        }                                                                        \
        CP_COMMIT;                                                               \
    }

    ACT_LOAD(0, 0);

    const int NIT = H_DIM / BK;
    for (int it = 0; it < NIT; ++it) {
        if (it + 1 < NIT) { ACT_LOAD((it + 1) & 1, (it + 1) * BK); CP_WAIT1; }
        else              { CP_WAIT0; }
        __syncthreads();

        float* cA  = sA  + (it & 1) * BM * LDA;
        float* cB1 = sB1 + (it & 1) * BK * LDB;
        float* cB2 = sB2 + (it & 1) * BK * LDB;
        #pragma unroll
        for (int kk = 0; kk < BK; kk += 8) {
            wmma::fragment<wmma::matrix_a, 16, 16, 8, wmma::precision::tf32, wmma::row_major> a[2];
            #pragma unroll
            for (int i = 0; i < 2; i++) {
                wmma::load_matrix_sync(a[i], cA + (wr * 32 + i * 16) * LDA + kk, LDA);
                #pragma unroll
                for (int q = 0; q < a[i].num_elements; q++) a[i].x[q] = wmma::__float_to_tf32(a[i].x[q]);
            }
            #pragma unroll
            for (int j = 0; j < 2; j++) {
                wmma::fragment<wmma::matrix_b, 16, 16, 8, wmma::precision::tf32, wmma::row_major> b1, b2;
                wmma::load_matrix_sync(b1, cB1 + kk * LDB + wc * 32 + j * 16, LDB);
                wmma::load_matrix_sync(b2, cB2 + kk * LDB + wc * 32 + j * 16, LDB);
                #pragma unroll
                for (int q = 0; q < b1.num_elements; q++) {
                    b1.x[q] = wmma::__float_to_tf32(b1.x[q]);
                    b2.x[q] = wmma::__float_to_tf32(b2.x[q]);
                }
                #pragma unroll
                for (int i = 0; i < 2; i++) {
                    wmma::mma_sync(acc1[i][j], a[i], b1, acc1[i][j]);
                    wmma::mma_sync(acc2[i][j], a[i], b2, acc2[i][j]);
                }
            }
        }
        __syncthreads();
    }
    #undef ACT_LOAD

    // epilogue: silu(g) * u
    #pragma unroll
    for (int i = 0; i < 2; i++)
        #pragma unroll
        for (int j = 0; j < 2; j++) {
            #pragma unroll
            for (int q = 0; q < acc1[i][j].num_elements; q++) {
                float g = acc1[i][j].x[q], u = acc2[i][j].x[q];
                acc1[i][j].x[q] = (g / (1.f + __expf(-g))) * u;
            }
            wmma::store_matrix_sync(
                outE + (size_t)(m0 + wr * 32 + i * 16) * nld + n0 + wc * 32 + j * 16,
                acc1[i][j], nld, wmma::mem_row_major);
        }
}

// ---------------------------------------------------------------------------
// Down GEMM: C = act @ Wdown. ROUTED: weighted atomic scatter; else plain store.
// dyn smem: sA[2][BM*LDA], sB[2][BK*LDB]; epilogue reuses smem as sC[BM][LDB]
template <bool ROUTED, int KDIM>
__global__ void __launch_bounds__(256)
down_kernel(const float* __restrict__ Abase,
            const float* __restrict__ Bbase,
            float* __restrict__ out) {
    extern __shared__ float smem[];
    float* sA = smem;                   // 2 * BM*LDA
    float* sB = smem + 2 * BM * LDA;    // 2 * BK*LDB
    __shared__ int   stok[BM];
    __shared__ float sw[BM];

    int e = ROUTED ? blockIdx.z : 0;
    int cnt = ROUTED ? g_count[e] : T_TOK;
    int m0 = blockIdx.y * BM;
    if (m0 >= cnt) return;
    int n0 = blockIdx.x * BN;
    int tid = threadIdx.x;

    if (ROUTED && tid < BM) {
        int slot = m0 + tid;
        bool v = slot < cnt;
        stok[tid] = v ? g_perm[e * T_TOK + slot] : -1;
        sw[tid]   = v ? g_wgt [e * T_TOK + slot] : 0.f;
    }

    const float* A = Abase + (ROUTED ? (size_t)e * T_TOK * KDIM : 0);
    const float* B = Bbase + (ROUTED ? (size_t)e * KDIM * H_DIM : 0);

    int warp = tid >> 5;
    int wr = warp & 1;
    int wc = warp >> 1;

    wmma::fragment<wmma::accumulator, 16, 16, 8, float> acc[2][2];
    #pragma unroll
    for (int i = 0; i < 2; i++)
        #pragma unroll
        for (int j = 0; j < 2; j++) wmma::fill_fragment(acc[i][j], 0.f);

    int rA = tid >> 3, cA4 = (tid & 7) * 4;
    int rB = tid >> 5, cB4 = (tid & 31) * 4;

    #define DOWN_LOAD(st, k0)                                                    \
    {                                                                            \
        _Pragma("unroll")                                                        \
        for (int i = 0; i < 2; i++) {                                            \
            int r = rA + i * 32;                                                 \
            cpa16(sA + (st) * BM * LDA + r * LDA + cA4,                          \
                  A + (size_t)(m0 + r) * KDIM + (k0) + cA4);                     \
        }                                                                        \
        _Pragma("unroll")                                                        \
        for (int i = 0; i < 4; i++) {                                            \
            int r = rB + i * 8;                                                  \
            cpa16(sB + (st) * BK * LDB + r * LDB + cB4,                          \
                  B + (size_t)((k0) + r) * H_DIM + n0 + cB4);                    \
        }                                                                        \
        CP_COMMIT;                                                               \
    }

    DOWN_LOAD(0, 0);

    const int NIT = KDIM / BK;
    for (int it = 0; it < NIT; ++it) {
        if (it + 1 < NIT) { DOWN_LOAD((it + 1) & 1, (it + 1) * BK); CP_WAIT1; }
        else              { CP_WAIT0; }
        __syncthreads();

        float* cA = sA + (it & 1) * BM * LDA;
        float* cB = sB + (it & 1) * BK * LDB;
        #pragma unroll
        for (int kk = 0; kk < BK; kk += 8) {
            wmma::fragment<wmma::matrix_a, 16, 16, 8, wmma::precision::tf32, wmma::row_major> a[2];
            #pragma unroll
            for (int i = 0; i < 2; i++) {
                wmma::load_matrix_sync(a[i], cA + (wr * 32 + i * 16) * LDA + kk, LDA);
                #pragma unroll
                for (int q = 0; q < a[i].num_elements; q++) a[i].x[q] = wmma::__float_to_tf32(a[i].x[q]);
            }
            #pragma unroll
            for (int j = 0; j < 2; j++) {
                wmma::fragment<wmma::matrix_b, 16, 16, 8, wmma::precision::tf32, wmma::row_major> b;
                wmma::load_matrix_sync(b, cB + kk * LDB + wc * 32 + j * 16, LDB);
                #pragma unroll
                for (int q = 0; q < b.num_elements; q++) b.x[q] = wmma::__float_to_tf32(b.x[q]);
                #pragma unroll
                for (int i = 0; i < 2; i++)
                    wmma::mma_sync(acc[i][j], a[i], b, acc[i][j]);
            }
        }
        __syncthreads();
    }
    #undef DOWN_LOAD

    // epilogue: stage 64x128 tile in smem, then drain coalesced
    float* sC = smem;   // BM * LDB floats needed (8448) <= 13056 available
    #pragma unroll
    for (int i = 0; i < 2; i++)
        #pragma unroll
        for (int j = 0; j < 2; j++)
            wmma::store_matrix_sync(sC + (wr * 32 + i * 16) * LDB + wc * 32 + j * 16,
                                    acc[i][j], LDB, wmma::mem_row_major);
    __syncthreads();

    for (int idx = tid; idx < BM * BN; idx += 256) {
        int r = idx >> 7, c = idx & (BN - 1);
        float v = sC[r * LDB + c];
        if (ROUTED) {
            int tok = stok[r];
            if (tok >= 0)
                atomicAdd(out + (size_t)tok * H_DIM + n0 + c, sw[r] * v);
        } else {
            out[(size_t)(m0 + r) * H_DIM + n0 + c] = v;
        }
    }
}

// ---------------------------------------------------------------------------
extern "C" void kernel_launch(void* const* d_in, const int* in_sizes, int n_in,
                              void* d_out, int out_size) {
    const float* x  = (const float*)d_in[0];
    const float* gw = (const float*)d_in[1];
    const float* gp = (const float*)d_in[2];
    const float* up = (const float*)d_in[3];
    const float* dp = (const float*)d_in[4];
    const float* sg = (const float*)d_in[5];
    const float* su = (const float*)d_in[6];
    const float* sd = (const float*)d_in[7];
    float* out = (float*)d_out;

    float* actPtr;  cudaGetSymbolAddress((void**)&actPtr,  g_act);
    float* sactPtr; cudaGetSymbolAddress((void**)&sactPtr, g_sact);

    const int actSmem  = (2 * BM * LDA + 4 * BK * LDB) * sizeof(float);   // 86016
    const int downSmem = (2 * BM * LDA + 2 * BK * LDB) * sizeof(float);   // 52224
    cudaFuncSetAttribute(act_kernel<true>,  cudaFuncAttributeMaxDynamicSharedMemorySize, actSmem);
    cudaFuncSetAttribute(act_kernel<false>, cudaFuncAttributeMaxDynamicSharedMemorySize, actSmem);
    cudaFuncSetAttribute((const void*)down_kernel<false, SF_DIM>, cudaFuncAttributeMaxDynamicSharedMemorySize, downSmem);
    cudaFuncSetAttribute((const void*)down_kernel<true,  F_DIM>,  cudaFuncAttributeMaxDynamicSharedMemorySize, downSmem);

    zero_counts_kernel<<<1, 32>>>();
    gate_topk_kernel<<<T_TOK, 256>>>(x, gw);

    act_kernel<true><<<dim3(F_DIM / BN, T_TOK / BM, N_EXP), 256, actSmem>>>(x, gp, up, actPtr, F_DIM);
    act_kernel<false><<<dim3(SF_DIM / BN, T_TOK / BM, 1), 256, actSmem>>>(x, sg, su, sactPtr, SF_DIM);

    down_kernel<false, SF_DIM><<<dim3(H_DIM / BN, T_TOK / BM, 1), 256, downSmem>>>(sactPtr, sd, out);
    down_kernel<true,  F_DIM><<<dim3(H_DIM / BN, T_TOK / BM, N_EXP), 256, downSmem>>>(actPtr, dp, out);
}

// round 6
// speedup vs baseline: 3.3369x; 2.0642x over previous
#include <cuda_runtime.h>
#include <cstdint>

#define T_TOK 2048
#define H_DIM 2048
#define F_DIM 1408
#define SF_DIM 2816
#define N_EXP 8

#define BK 32
#define STAGES 3
#define LDA 36     // 32 + 4 pad (144B rows)
#define LDB 136    // 128 + 8 pad (544B rows)
#define ACT_STAGE_F (128 * LDA + 2 * BK * LDB)   // 13312 floats
#define DOWN_STAGE_F (128 * LDA + BK * LDB)      // 8960 floats
#define ACT_SMEM (STAGES * ACT_STAGE_F * 4)      // 159744 B
#define DOWN_SMEM (STAGES * DOWN_STAGE_F * 4)    // 107520 B

// ---- scratch (device globals: no allocations allowed) ----
__device__ int   g_count[N_EXP];
__device__ int   g_perm[N_EXP * T_TOK];
__device__ float g_wgt [N_EXP * T_TOK];
__device__ float g_act [(size_t)N_EXP * T_TOK * F_DIM];
__device__ float g_sact[(size_t)T_TOK * SF_DIM];
// tf32-rounded copies (prepass)
__device__ float g_xr [(size_t)T_TOK * H_DIM];
__device__ float g_gp [(size_t)N_EXP * H_DIM * F_DIM];
__device__ float g_up [(size_t)N_EXP * H_DIM * F_DIM];
__device__ float g_dp [(size_t)N_EXP * F_DIM * H_DIM];
__device__ float g_sg [(size_t)H_DIM * SF_DIM];
__device__ float g_su [(size_t)H_DIM * SF_DIM];
__device__ float g_sd [(size_t)SF_DIM * H_DIM];

// ---------------------------------------------------------------------------
__device__ __forceinline__ uint32_t smem_u32(const void* p) {
    uint32_t a;
    asm("{ .reg .u64 t; cvta.to.shared.u64 t, %1; cvt.u32.u64 %0, t; }" : "=r"(a) : "l"(p));
    return a;
}
__device__ __forceinline__ void cpa16s(uint32_t sa, const void* g) {
    asm volatile("cp.async.cg.shared.global [%0], [%1], 16;" :: "r"(sa), "l"(g));
}
#define CP_COMMIT asm volatile("cp.async.commit_group;" ::: "memory")
#define CP_WAIT(n) asm volatile("cp.async.wait_group %0;" :: "n"(n) : "memory")

__device__ __forceinline__ uint32_t f2tf32(float v) {
    uint32_t u;
    asm("cvt.rna.tf32.f32 %0, %1;" : "=r"(u) : "f"(v));
    return u;
}

__device__ __forceinline__ void mma8(float* c, const uint32_t* a, uint32_t b0, uint32_t b1) {
    asm volatile(
        "mma.sync.aligned.m16n8k8.row.col.f32.tf32.tf32.f32 "
        "{%0,%1,%2,%3}, {%4,%5,%6,%7}, {%8,%9}, {%0,%1,%2,%3};"
        : "+f"(c[0]), "+f"(c[1]), "+f"(c[2]), "+f"(c[3])
        : "r"(a[0]), "r"(a[1]), "r"(a[2]), "r"(a[3]), "r"(b0), "r"(b1));
}

// ---------------------------------------------------------------------------
__global__ void zero_counts_kernel() {
    if (threadIdx.x < N_EXP) g_count[threadIdx.x] = 0;
}

// round a tensor to tf32 (RN) into scratch
__global__ void round_tf32_kernel(const float4* __restrict__ in,
                                  float4* __restrict__ outp, int n4) {
    int stride = gridDim.x * blockDim.x;
    for (int i = blockIdx.x * blockDim.x + threadIdx.x; i < n4; i += stride) {
        float4 v = in[i];
        uint4 u;
        u.x = f2tf32(v.x); u.y = f2tf32(v.y); u.z = f2tf32(v.z); u.w = f2tf32(v.w);
        *(uint4*)(outp + i) = u;
    }
}

// ---------------------------------------------------------------------------
__global__ void gate_topk_kernel(const float* __restrict__ x,
                                 const float* __restrict__ gw) {
    __shared__ float xs[H_DIM];
    __shared__ float logits[N_EXP];
    int t = blockIdx.x;
    const float4* xr = (const float4*)(x + (size_t)t * H_DIM);
    for (int i = threadIdx.x; i < H_DIM / 4; i += blockDim.x)
        ((float4*)xs)[i] = xr[i];
    __syncthreads();

    int w = threadIdx.x >> 5, lane = threadIdx.x & 31;
    if (w < N_EXP) {
        const float* gr = gw + (size_t)w * H_DIM;
        float s = 0.f;
        for (int i = lane; i < H_DIM; i += 32) s += xs[i] * gr[i];
        #pragma unroll
        for (int o = 16; o; o >>= 1) s += __shfl_xor_sync(0xffffffffu, s, o);
        if (lane == 0) logits[w] = s;
    }
    __syncthreads();

    if (threadIdx.x == 0) {
        float m = logits[0];
        #pragma unroll
        for (int e = 1; e < N_EXP; e++) m = fmaxf(m, logits[e]);
        float p[N_EXP]; float sum = 0.f;
        #pragma unroll
        for (int e = 0; e < N_EXP; e++) { p[e] = expf(logits[e] - m); sum += p[e]; }
        float inv = 1.f / sum;
        int i0 = 0;
        #pragma unroll
        for (int e = 1; e < N_EXP; e++) if (p[e] > p[i0]) i0 = e;
        int i1 = (i0 == 0) ? 1 : 0;
        #pragma unroll
        for (int e = 0; e < N_EXP; e++) if (e != i0 && p[e] > p[i1]) i1 = e;

        int s0 = atomicAdd(&g_count[i0], 1);
        g_perm[i0 * T_TOK + s0] = t;
        g_wgt [i0 * T_TOK + s0] = p[i0] * inv;
        int s1 = atomicAdd(&g_count[i1], 1);
        g_perm[i1 * T_TOK + s1] = t;
        g_wgt [i1 * T_TOK + s1] = p[i1] * inv;
    }
}

// ---------------------------------------------------------------------------
// act: out = tf32_round( silu(A@W1) * (A@W2) ), block 128x128, warp 64x32.
// A gathered token rows (tf32-rounded x); W [K][N] row-major, K = H_DIM.
template <bool ROUTED>
__global__ void __launch_bounds__(256)
act_kernel(const float* __restrict__ x,
           const float* __restrict__ W1base,
           const float* __restrict__ W2base,
           float* __restrict__ outBase,
           int nld) {
    extern __shared__ float smem[];
    __shared__ int stok[128];

    int e = ROUTED ? blockIdx.z : 0;
    int cnt = ROUTED ? g_count[e] : T_TOK;
    int m0 = blockIdx.y * 128;
    if (m0 >= cnt) return;
    int n0 = blockIdx.x * 128;
    int tid = threadIdx.x, wid = tid >> 5, lane = tid & 31;
    int g = lane >> 2, tg = lane & 3;
    int wm = wid & 1, wn = wid >> 1;

    if (tid < 128) {
        int slot = m0 + tid;
        stok[tid] = ROUTED ? ((slot < cnt) ? g_perm[e * T_TOK + slot]
                                           : g_perm[e * T_TOK]) : slot;
    }
    __syncthreads();

    const float* W1 = W1base + (ROUTED ? (size_t)e * H_DIM * nld : 0);
    const float* W2 = W2base + (ROUTED ? (size_t)e * H_DIM * nld : 0);
    float* outE = outBase + (ROUTED ? (size_t)e * T_TOK * nld : 0);
    uint32_t sbase = smem_u32(smem);

    #define ACT_LOAD(st, k0) {                                                  \
        uint32_t aB = sbase + (st) * (ACT_STAGE_F * 4);                         \
        uint32_t b1B = aB + 128 * LDA * 4;                                      \
        uint32_t b2B = b1B + BK * LDB * 4;                                      \
        _Pragma("unroll")                                                       \
        for (int i = 0; i < 4; i++) {                                           \
            int c = tid + i * 256; int r = c >> 3, j = c & 7;                   \
            cpa16s(aB + r * (LDA * 4) + j * 16,                                 \
                   x + (size_t)stok[r] * H_DIM + (k0) + j * 4);                 \
        }                                                                       \
        _Pragma("unroll")                                                       \
        for (int i = 0; i < 4; i++) {                                           \
            int c = tid + i * 256; int r = c >> 5, j = c & 31;                  \
            size_t go = (size_t)((k0) + r) * nld + n0 + j * 4;                  \
            cpa16s(b1B + r * (LDB * 4) + j * 16, W1 + go);                      \
            cpa16s(b2B + r * (LDB * 4) + j * 16, W2 + go);                      \
        }                                                                       \
        CP_COMMIT;                                                              \
    }

    float acc1[4][4][4], acc2[4][4][4];
    #pragma unroll
    for (int mt = 0; mt < 4; mt++)
        #pragma unroll
        for (int nt = 0; nt < 4; nt++)
            #pragma unroll
            for (int q = 0; q < 4; q++) { acc1[mt][nt][q] = 0.f; acc2[mt][nt][q] = 0.f; }

    const int NIT = H_DIM / BK;   // 64
    ACT_LOAD(0, 0);
    ACT_LOAD(1, BK);

    for (int it = 0; it < NIT; ++it) {
        if (it + 1 < NIT) CP_WAIT(1); else CP_WAIT(0);
        __syncthreads();
        if (it + 2 < NIT) ACT_LOAD((it + 2) % STAGES, (it + 2) * BK);

        const uint32_t* uA  = (const uint32_t*)(smem + (it % STAGES) * ACT_STAGE_F);
        const uint32_t* uB1 = uA + 128 * LDA;
        const uint32_t* uB2 = uB1 + BK * LDB;

        #pragma unroll
        for (int kk = 0; kk < BK; kk += 8) {
            uint32_t a[4][4];
            #pragma unroll
            for (int mt = 0; mt < 4; mt++) {
                int r0 = (wm * 64 + mt * 16 + g) * LDA + kk + tg;
                a[mt][0] = uA[r0];
                a[mt][1] = uA[r0 + 8 * LDA];
                a[mt][2] = uA[r0 + 4];
                a[mt][3] = uA[r0 + 8 * LDA + 4];
            }
            #pragma unroll
            for (int nt = 0; nt < 4; nt++) {
                int bo = (kk + tg) * LDB + wn * 32 + nt * 8 + g;
                uint32_t b10 = uB1[bo], b11 = uB1[bo + 4 * LDB];
                uint32_t b20 = uB2[bo], b21 = uB2[bo + 4 * LDB];
                #pragma unroll
                for (int mt = 0; mt < 4; mt++) {
                    mma8(acc1[mt][nt], a[mt], b10, b11);
                    mma8(acc2[mt][nt], a[mt], b20, b21);
                }
            }
        }
    }
    #undef ACT_LOAD

    // epilogue: silu(g)*u, round to tf32, store
    #pragma unroll
    for (int mt = 0; mt < 4; mt++) {
        #pragma unroll
        for (int nt = 0; nt < 4; nt++) {
            uint32_t o[4];
            #pragma unroll
            for (int q = 0; q < 4; q++) {
                float gv = acc1[mt][nt][q], uv = acc2[mt][nt][q];
                o[q] = f2tf32((gv / (1.f + __expf(-gv))) * uv);
            }
            int row = m0 + wm * 64 + mt * 16 + g;
            int col = n0 + wn * 32 + nt * 8 + tg * 2;
            *(uint2*)(outE + (size_t)row * nld + col)       = make_uint2(o[0], o[1]);
            *(uint2*)(outE + (size_t)(row + 8) * nld + col) = make_uint2(o[2], o[3]);
        }
    }
}

// ---------------------------------------------------------------------------
// down: C = A @ Wd, block 128x128, warp 64x32.
// ROUTED: weighted atomic scatter-add; else plain store.
template <bool ROUTED>
__global__ void __launch_bounds__(256)
down_kernel(const float* __restrict__ Abase,
            const float* __restrict__ Bbase,
            float* __restrict__ out,
            int KD) {
    extern __shared__ float smem[];
    __shared__ int   stok[128];
    __shared__ float swt[128];

    int e = ROUTED ? blockIdx.z : 0;
    int cnt = ROUTED ? g_count[e] : T_TOK;
    int m0 = blockIdx.y * 128;
    if (m0 >= cnt) return;
    int n0 = blockIdx.x * 128;
    int tid = threadIdx.x, wid = tid >> 5, lane = tid & 31;
    int g = lane >> 2, tg = lane & 3;
    int wm = wid & 1, wn = wid >> 1;

    if (ROUTED && tid < 128) {
        int slot = m0 + tid;
        bool v = slot < cnt;
        stok[tid] = v ? g_perm[e * T_TOK + slot] : -1;
        swt[tid]  = v ? g_wgt [e * T_TOK + slot] : 0.f;
    }
    __syncthreads();

    const float* A = Abase + (ROUTED ? (size_t)e * T_TOK * KD : 0);
    const float* B = Bbase + (ROUTED ? (size_t)e * KD * H_DIM : 0);
    uint32_t sbase = smem_u32(smem);

    #define DOWN_LOAD(st, k0) {                                                 \
        uint32_t aB = sbase + (st) * (DOWN_STAGE_F * 4);                        \
        uint32_t bB = aB + 128 * LDA * 4;                                       \
        _Pragma("unroll")                                                       \
        for (int i = 0; i < 4; i++) {                                           \
            int c = tid + i * 256; int r = c >> 3, j = c & 7;                   \
            cpa16s(aB + r * (LDA * 4) + j * 16,                                 \
                   A + (size_t)(m0 + r) * KD + (k0) + j * 4);                   \
        }                                                                       \
        _Pragma("unroll")                                                       \
        for (int i = 0; i < 4; i++) {                                           \
            int c = tid + i * 256; int r = c >> 5, j = c & 31;                  \
            cpa16s(bB + r * (LDB * 4) + j * 16,                                 \
                   B + (size_t)((k0) + r) * H_DIM + n0 + j * 4);                \
        }                                                                       \
        CP_COMMIT;                                                              \
    }

    float acc[4][4][4];
    #pragma unroll
    for (int mt = 0; mt < 4; mt++)
        #pragma unroll
        for (int nt = 0; nt < 4; nt++)
            #pragma unroll
            for (int q = 0; q < 4; q++) acc[mt][nt][q] = 0.f;

    const int NIT = KD / BK;
    DOWN_LOAD(0, 0);
    DOWN_LOAD(1, BK);

    for (int it = 0; it < NIT; ++it) {
        if (it + 1 < NIT) CP_WAIT(1); else CP_WAIT(0);
        __syncthreads();
        if (it + 2 < NIT) DOWN_LOAD((it + 2) % STAGES, (it + 2) * BK);

        const uint32_t* uA = (const uint32_t*)(smem + (it % STAGES) * DOWN_STAGE_F);
        const uint32_t* uB = uA + 128 * LDA;

        #pragma unroll
        for (int kk = 0; kk < BK; kk += 8) {
            uint32_t a[4][4];
            #pragma unroll
            for (int mt = 0; mt < 4; mt++) {
                int r0 = (wm * 64 + mt * 16 + g) * LDA + kk + tg;
                a[mt][0] = uA[r0];
                a[mt][1] = uA[r0 + 8 * LDA];
                a[mt][2] = uA[r0 + 4];
                a[mt][3] = uA[r0 + 8 * LDA + 4];
            }
            #pragma unroll
            for (int nt = 0; nt < 4; nt++) {
                int bo = (kk + tg) * LDB + wn * 32 + nt * 8 + g;
                uint32_t b0 = uB[bo], b1 = uB[bo + 4 * LDB];
                #pragma unroll
                for (int mt = 0; mt < 4; mt++)
                    mma8(acc[mt][nt], a[mt], b0, b1);
            }
        }
    }
    #undef DOWN_LOAD

    #pragma unroll
    for (int mt = 0; mt < 4; mt++) {
        int rl0 = wm * 64 + mt * 16 + g;
        #pragma unroll
        for (int half = 0; half < 2; half++) {
            int rl = rl0 + half * 8;
            if (ROUTED) {
                int tok = stok[rl];
                if (tok < 0) continue;
                float w = swt[rl];
                float* dst = out + (size_t)tok * H_DIM + n0;
                #pragma unroll
                for (int nt = 0; nt < 4; nt++) {
                    int col = wn * 32 + nt * 8 + tg * 2;
                    atomicAdd(dst + col,     w * acc[mt][nt][half * 2 + 0]);
                    atomicAdd(dst + col + 1, w * acc[mt][nt][half * 2 + 1]);
                }
            } else {
                float* dst = out + (size_t)(m0 + rl) * H_DIM + n0;
                #pragma unroll
                for (int nt = 0; nt < 4; nt++) {
                    int col = wn * 32 + nt * 8 + tg * 2;
                    *(float2*)(dst + col) =
                        make_float2(acc[mt][nt][half * 2 + 0], acc[mt][nt][half * 2 + 1]);
                }
            }
        }
    }
}

// ---------------------------------------------------------------------------
extern "C" void kernel_launch(void* const* d_in, const int* in_sizes, int n_in,
                              void* d_out, int out_size) {
    const float* x  = (const float*)d_in[0];
    const float* gw = (const float*)d_in[1];
    const float* gp = (const float*)d_in[2];
    const float* up = (const float*)d_in[3];
    const float* dp = (const float*)d_in[4];
    const float* sg = (const float*)d_in[5];
    const float* su = (const float*)d_in[6];
    const float* sd = (const float*)d_in[7];
    float* out = (float*)d_out;

    float *actP, *sactP, *xrP, *gpP, *upP, *dpP, *sgP, *suP, *sdP;
    cudaGetSymbolAddress((void**)&actP,  g_act);
    cudaGetSymbolAddress((void**)&sactP, g_sact);
    cudaGetSymbolAddress((void**)&xrP,   g_xr);
    cudaGetSymbolAddress((void**)&gpP,   g_gp);
    cudaGetSymbolAddress((void**)&upP,   g_up);
    cudaGetSymbolAddress((void**)&dpP,   g_dp);
    cudaGetSymbolAddress((void**)&sgP,   g_sg);
    cudaGetSymbolAddress((void**)&suP,   g_su);
    cudaGetSymbolAddress((void**)&sdP,   g_sd);

    cudaFuncSetAttribute(act_kernel<true>,   cudaFuncAttributeMaxDynamicSharedMemorySize, ACT_SMEM);
    cudaFuncSetAttribute(act_kernel<false>,  cudaFuncAttributeMaxDynamicSharedMemorySize, ACT_SMEM);
    cudaFuncSetAttribute(down_kernel<true>,  cudaFuncAttributeMaxDynamicSharedMemorySize, DOWN_SMEM);
    cudaFuncSetAttribute(down_kernel<false>, cudaFuncAttributeMaxDynamicSharedMemorySize, DOWN_SMEM);

    zero_counts_kernel<<<1, 32>>>();
    gate_topk_kernel<<<T_TOK, 256>>>(x, gw);

    // prepass: round operands to tf32 (RN) so mainloops need no conversions
    const int RB = 2048, RT = 256;
    round_tf32_kernel<<<RB, RT>>>((const float4*)x,  (float4*)xrP, (T_TOK * H_DIM) / 4);
    round_tf32_kernel<<<RB, RT>>>((const float4*)gp, (float4*)gpP, (N_EXP * H_DIM * F_DIM) / 4);
    round_tf32_kernel<<<RB, RT>>>((const float4*)up, (float4*)upP, (N_EXP * H_DIM * F_DIM) / 4);
    round_tf32_kernel<<<RB, RT>>>((const float4*)dp, (float4*)dpP, (N_EXP * F_DIM * H_DIM) / 4);
    round_tf32_kernel<<<RB, RT>>>((const float4*)sg, (float4*)sgP, (H_DIM * SF_DIM) / 4);
    round_tf32_kernel<<<RB, RT>>>((const float4*)su, (float4*)suP, (H_DIM * SF_DIM) / 4);
    round_tf32_kernel<<<RB, RT>>>((const float4*)sd, (float4*)sdP, (SF_DIM * H_DIM) / 4);

    act_kernel<true><<<dim3(F_DIM / 128, T_TOK / 128, N_EXP), 256, ACT_SMEM>>>(xrP, gpP, upP, actP, F_DIM);
    act_kernel<false><<<dim3(SF_DIM / 128, T_TOK / 128, 1), 256, ACT_SMEM>>>(xrP, sgP, suP, sactP, SF_DIM);

    down_kernel<false><<<dim3(H_DIM / 128, T_TOK / 128, 1), 256, DOWN_SMEM>>>(sactP, sdP, out, SF_DIM);
    down_kernel<true><<<dim3(H_DIM / 128, T_TOK / 128, N_EXP), 256, DOWN_SMEM>>>(actP, dpP, out, F_DIM);
}

// round 7
// speedup vs baseline: 4.9300x; 1.4774x over previous
#include <cuda_runtime.h>
#include <cuda_fp16.h>
#include <cstdint>

#define T_TOK 2048
#define H_DIM 2048
#define F_DIM 1408
#define SF_DIM 2816
#define N_EXP 8

#define BK 32
#define STAGES 3
#define LDH 40                                   // halves per smem row (80B pitch)
#define ACT_STAGE_H (384 * LDH)                  // A(128) + B1(128) + B2(128) rows
#define DOWN_STAGE_H (256 * LDH)                 // A(128) + B(128)
#define ACT_SMEM (STAGES * ACT_STAGE_H * 2)      // 92160 B
#define DOWN_SMEM (STAGES * DOWN_STAGE_H * 2)    // 61440 B

// ---- scratch (device globals: no allocations allowed) ----
__device__ int    g_count[N_EXP];
__device__ int    g_perm[N_EXP * T_TOK];
__device__ float  g_wgt [N_EXP * T_TOK];
__device__ __half g_xh  [(size_t)T_TOK * H_DIM];           // x fp16 [T][H]
__device__ __half g_w1t [(size_t)N_EXP * F_DIM * H_DIM];   // gate_proj^T [E][F][H]
__device__ __half g_w2t [(size_t)N_EXP * F_DIM * H_DIM];   // up_proj^T   [E][F][H]
__device__ __half g_wdt [(size_t)N_EXP * H_DIM * F_DIM];   // down_proj^T [E][H][F]
__device__ __half g_sgt [(size_t)SF_DIM * H_DIM];          // shared_gate^T [SF][H]
__device__ __half g_sut [(size_t)SF_DIM * H_DIM];          // shared_up^T   [SF][H]
__device__ __half g_sdt [(size_t)H_DIM * SF_DIM];          // shared_down^T [H][SF]
__device__ __half g_acth[(size_t)N_EXP * T_TOK * F_DIM];   // routed act fp16
__device__ __half g_sacth[(size_t)T_TOK * SF_DIM];         // shared act fp16

// ---------------------------------------------------------------------------
__device__ __forceinline__ uint32_t smem_u32(const void* p) {
    uint32_t a;
    asm("{ .reg .u64 t; cvta.to.shared.u64 t, %1; cvt.u32.u64 %0, t; }" : "=r"(a) : "l"(p));
    return a;
}
__device__ __forceinline__ void cpa16s(uint32_t sa, const void* g) {
    asm volatile("cp.async.cg.shared.global [%0], [%1], 16;" :: "r"(sa), "l"(g));
}
#define CP_COMMIT asm volatile("cp.async.commit_group;" ::: "memory")
#define CP_WAIT(n) asm volatile("cp.async.wait_group %0;" :: "n"(n) : "memory")

__device__ __forceinline__ void mma16(float* c, const uint32_t* a, uint32_t b0, uint32_t b1) {
    asm volatile(
        "mma.sync.aligned.m16n8k16.row.col.f32.f16.f16.f32 "
        "{%0,%1,%2,%3}, {%4,%5,%6,%7}, {%8,%9}, {%0,%1,%2,%3};"
        : "+f"(c[0]), "+f"(c[1]), "+f"(c[2]), "+f"(c[3])
        : "r"(a[0]), "r"(a[1]), "r"(a[2]), "r"(a[3]), "r"(b0), "r"(b1));
}

// ---------------------------------------------------------------------------
__global__ void zero_counts_kernel() {
    if (threadIdx.x < N_EXP) g_count[threadIdx.x] = 0;
}

// fp32 -> fp16, no transpose (for x)
__global__ void f2h_kernel(const float4* __restrict__ in, uint2* __restrict__ outp, int n4) {
    int stride = gridDim.x * blockDim.x;
    for (int i = blockIdx.x * blockDim.x + threadIdx.x; i < n4; i += stride) {
        float4 v = in[i];
        __half2 lo = __floats2half2_rn(v.x, v.y);
        __half2 hi = __floats2half2_rn(v.z, v.w);
        outp[i] = make_uint2(*(uint32_t*)&lo, *(uint32_t*)&hi);
    }
}

// fp32 [z][R][C] -> fp16 [z][C][R]
__global__ void transpose_f2h_kernel(const float* __restrict__ in,
                                     __half* __restrict__ outp, int R, int C) {
    __shared__ float t[32][33];
    int tx = threadIdx.x, ty = threadIdx.y;
    int c0 = blockIdx.x * 32, r0 = blockIdx.y * 32;
    size_t zo = (size_t)blockIdx.z * R * C;
    #pragma unroll
    for (int i = 0; i < 4; i++)
        t[ty + i * 8][tx] = in[zo + (size_t)(r0 + ty + i * 8) * C + c0 + tx];
    __syncthreads();
    #pragma unroll
    for (int i = 0; i < 4; i++)
        outp[zo + (size_t)(c0 + ty + i * 8) * R + r0 + tx] = __float2half(t[tx][ty + i * 8]);
}

// ---------------------------------------------------------------------------
__global__ void gate_topk_kernel(const float* __restrict__ x,
                                 const float* __restrict__ gw) {
    __shared__ float xs[H_DIM];
    __shared__ float logits[N_EXP];
    int t = blockIdx.x;
    const float4* xr = (const float4*)(x + (size_t)t * H_DIM);
    for (int i = threadIdx.x; i < H_DIM / 4; i += blockDim.x)
        ((float4*)xs)[i] = xr[i];
    __syncthreads();

    int w = threadIdx.x >> 5, lane = threadIdx.x & 31;
    if (w < N_EXP) {
        const float* gr = gw + (size_t)w * H_DIM;
        float s = 0.f;
        for (int i = lane; i < H_DIM; i += 32) s += xs[i] * gr[i];
        #pragma unroll
        for (int o = 16; o; o >>= 1) s += __shfl_xor_sync(0xffffffffu, s, o);
        if (lane == 0) logits[w] = s;
    }
    __syncthreads();

    if (threadIdx.x == 0) {
        float m = logits[0];
        #pragma unroll
        for (int e = 1; e < N_EXP; e++) m = fmaxf(m, logits[e]);
        float p[N_EXP]; float sum = 0.f;
        #pragma unroll
        for (int e = 0; e < N_EXP; e++) { p[e] = expf(logits[e] - m); sum += p[e]; }
        float inv = 1.f / sum;
        int i0 = 0;
        #pragma unroll
        for (int e = 1; e < N_EXP; e++) if (p[e] > p[i0]) i0 = e;
        int i1 = (i0 == 0) ? 1 : 0;
        #pragma unroll
        for (int e = 0; e < N_EXP; e++) if (e != i0 && p[e] > p[i1]) i1 = e;

        int s0 = atomicAdd(&g_count[i0], 1);
        g_perm[i0 * T_TOK + s0] = t;
        g_wgt [i0 * T_TOK + s0] = p[i0] * inv;
        int s1 = atomicAdd(&g_count[i1], 1);
        g_perm[i1 * T_TOK + s1] = t;
        g_wgt [i1 * T_TOK + s1] = p[i1] * inv;
    }
}

// ---------------------------------------------------------------------------
// act: out_fp16 = silu(A@W1t^T) * (A@W2t^T).  A fp16 [.][KD] k-contig (gathered
// rows), B fp16 [N][KD] k-contig (pre-transposed). block 128x128, warp 64x32.
template <bool ROUTED>
__global__ void __launch_bounds__(256)
act_kernel(const __half* __restrict__ Ax,
           const __half* __restrict__ B1base,
           const __half* __restrict__ B2base,
           __half* __restrict__ outBase,
           int nld) {    // nld = N total (out pitch); KD = H_DIM
    extern __shared__ __half smem[];
    __shared__ int stok[128];
    const int KD = H_DIM;

    int e = ROUTED ? blockIdx.z : 0;
    int cnt = ROUTED ? g_count[e] : T_TOK;
    int m0 = blockIdx.y * 128;
    if (m0 >= cnt) return;
    int n0 = blockIdx.x * 128;
    int tid = threadIdx.x, wid = tid >> 5, lane = tid & 31;
    int g = lane >> 2, tg = lane & 3;
    int wm = wid & 1, wn = wid >> 1;

    if (tid < 128) {
        int slot = m0 + tid;
        stok[tid] = ROUTED ? ((slot < cnt) ? g_perm[e * T_TOK + slot]
                                           : g_perm[e * T_TOK]) : slot;
    }
    __syncthreads();

    const __half* B1 = B1base + (ROUTED ? (size_t)e * F_DIM * H_DIM : 0);
    const __half* B2 = B2base + (ROUTED ? (size_t)e * F_DIM * H_DIM : 0);
    __half* outE = outBase + (ROUTED ? (size_t)e * T_TOK * nld : 0);
    uint32_t sbase = smem_u32(smem);

    // per stage: A rows [0,128), B1 rows [128,256), B2 rows [256,384), 80B pitch
    #define ACT_LOAD(st, k0) {                                                  \
        uint32_t base = sbase + (st) * (ACT_STAGE_H * 2);                       \
        _Pragma("unroll")                                                       \
        for (int i = 0; i < 2; i++) {                                           \
            int c = tid + i * 256; int r = c >> 2, j = c & 3;                   \
            cpa16s(base + r * 80 + j * 16,                                      \
                   Ax + (size_t)stok[r] * KD + (k0) + j * 8);                   \
        }                                                                       \
        _Pragma("unroll")                                                       \
        for (int i = 0; i < 2; i++) {                                           \
            int c = tid + i * 256; int r = c >> 2, j = c & 3;                   \
            size_t go = (size_t)(n0 + r) * KD + (k0) + j * 8;                   \
            cpa16s(base + (128 + r) * 80 + j * 16, B1 + go);                    \
            cpa16s(base + (256 + r) * 80 + j * 16, B2 + go);                    \
        }                                                                       \
        CP_COMMIT;                                                              \
    }

    float acc1[4][4][4], acc2[4][4][4];
    #pragma unroll
    for (int mt = 0; mt < 4; mt++)
        #pragma unroll
        for (int nt = 0; nt < 4; nt++)
            #pragma unroll
            for (int q = 0; q < 4; q++) { acc1[mt][nt][q] = 0.f; acc2[mt][nt][q] = 0.f; }

    const int NIT = KD / BK;   // 64
    ACT_LOAD(0, 0);
    ACT_LOAD(1, BK);

    for (int it = 0; it < NIT; ++it) {
        if (it + 1 < NIT) CP_WAIT(1); else CP_WAIT(0);
        __syncthreads();
        if (it + 2 < NIT) ACT_LOAD((it + 2) % STAGES, (it + 2) * BK);

        const uint32_t* uS = (const uint32_t*)(smem + (it % STAGES) * ACT_STAGE_H);
        const uint32_t* uB1 = uS + 128 * 20;
        const uint32_t* uB2 = uS + 256 * 20;

        #pragma unroll
        for (int kk2 = 0; kk2 < 16; kk2 += 8) {   // two k16 steps
            uint32_t a[4][4];
            #pragma unroll
            for (int mt = 0; mt < 4; mt++) {
                int r0 = (wm * 64 + mt * 16 + g) * 20 + kk2 + tg;
                a[mt][0] = uS[r0];
                a[mt][1] = uS[r0 + 8 * 20];
                a[mt][2] = uS[r0 + 4];
                a[mt][3] = uS[r0 + 8 * 20 + 4];
            }
            #pragma unroll
            for (int nt = 0; nt < 4; nt++) {
                int bo = (wn * 32 + nt * 8 + g) * 20 + kk2 + tg;
                uint32_t b10 = uB1[bo], b11 = uB1[bo + 4];
                uint32_t b20 = uB2[bo], b21 = uB2[bo + 4];
                #pragma unroll
                for (int mt = 0; mt < 4; mt++) {
                    mma16(acc1[mt][nt], a[mt], b10, b11);
                    mma16(acc2[mt][nt], a[mt], b20, b21);
                }
            }
        }
    }
    #undef ACT_LOAD

    // epilogue: silu(g)*u -> fp16
    #pragma unroll
    for (int mt = 0; mt < 4; mt++) {
        #pragma unroll
        for (int nt = 0; nt < 4; nt++) {
            float v[4];
            #pragma unroll
            for (int q = 0; q < 4; q++) {
                float gv = acc1[mt][nt][q], uv = acc2[mt][nt][q];
                v[q] = (gv / (1.f + __expf(-gv))) * uv;
            }
            __half2 lo = __floats2half2_rn(v[0], v[1]);
            __half2 hi = __floats2half2_rn(v[2], v[3]);
            int row = m0 + wm * 64 + mt * 16 + g;
            int col = n0 + wn * 32 + nt * 8 + tg * 2;
            *(uint32_t*)(outE + (size_t)row * nld + col)       = *(uint32_t*)&lo;
            *(uint32_t*)(outE + (size_t)(row + 8) * nld + col) = *(uint32_t*)&hi;
        }
    }
}

// ---------------------------------------------------------------------------
// down: C = A @ Wd (B pre-transposed [H][KD] k-contig). block 128x128, warp 64x32.
template <bool ROUTED>
__global__ void __launch_bounds__(256)
down_kernel(const __half* __restrict__ Abase,
            const __half* __restrict__ Bbase,
            float* __restrict__ out,
            int KD) {
    extern __shared__ __half smem[];
    __shared__ int   stok[128];
    __shared__ float swt[128];

    int e = ROUTED ? blockIdx.z : 0;
    int cnt = ROUTED ? g_count[e] : T_TOK;
    int m0 = blockIdx.y * 128;
    if (m0 >= cnt) return;
    int n0 = blockIdx.x * 128;
    int tid = threadIdx.x, wid = tid >> 5, lane = tid & 31;
    int g = lane >> 2, tg = lane & 3;
    int wm = wid & 1, wn = wid >> 1;

    if (ROUTED && tid < 128) {
        int slot = m0 + tid;
        bool v = slot < cnt;
        stok[tid] = v ? g_perm[e * T_TOK + slot] : -1;
        swt[tid]  = v ? g_wgt [e * T_TOK + slot] : 0.f;
    }
    __syncthreads();

    const __half* A = Abase + (ROUTED ? (size_t)e * T_TOK * KD : 0);
    const __half* B = Bbase + (ROUTED ? (size_t)e * H_DIM * KD : 0);
    uint32_t sbase = smem_u32(smem);

    #define DOWN_LOAD(st, k0) {                                                 \
        uint32_t base = sbase + (st) * (DOWN_STAGE_H * 2);                      \
        _Pragma("unroll")                                                       \
        for (int i = 0; i < 2; i++) {                                           \
            int c = tid + i * 256; int r = c >> 2, j = c & 3;                   \
            cpa16s(base + r * 80 + j * 16,                                      \
                   A + (size_t)(m0 + r) * KD + (k0) + j * 8);                   \
        }                                                                       \
        _Pragma("unroll")                                                       \
        for (int i = 0; i < 2; i++) {                                           \
            int c = tid + i * 256; int r = c >> 2, j = c & 3;                   \
            cpa16s(base + (128 + r) * 80 + j * 16,                              \
                   B + (size_t)(n0 + r) * KD + (k0) + j * 8);                   \
        }                                                                       \
        CP_COMMIT;                                                              \
    }

    float acc[4][4][4];
    #pragma unroll
    for (int mt = 0; mt < 4; mt++)
        #pragma unroll
        for (int nt = 0; nt < 4; nt++)
            #pragma unroll
            for (int q = 0; q < 4; q++) acc[mt][nt][q] = 0.f;

    const int NIT = KD / BK;   // 44 or 88
    DOWN_LOAD(0, 0);
    DOWN_LOAD(1, BK);

    for (int it = 0; it < NIT; ++it) {
        if (it + 1 < NIT) CP_WAIT(1); else CP_WAIT(0);
        __syncthreads();
        if (it + 2 < NIT) DOWN_LOAD((it + 2) % STAGES, (it + 2) * BK);

        const uint32_t* uS = (const uint32_t*)(smem + (it % STAGES) * DOWN_STAGE_H);
        const uint32_t* uB = uS + 128 * 20;

        #pragma unroll
        for (int kk2 = 0; kk2 < 16; kk2 += 8) {
            uint32_t a[4][4];
            #pragma unroll
            for (int mt = 0; mt < 4; mt++) {
                int r0 = (wm * 64 + mt * 16 + g) * 20 + kk2 + tg;
                a[mt][0] = uS[r0];
                a[mt][1] = uS[r0 + 8 * 20];
                a[mt][2] = uS[r0 + 4];
                a[mt][3] = uS[r0 + 8 * 20 + 4];
            }
            #pragma unroll
            for (int nt = 0; nt < 4; nt++) {
                int bo = (wn * 32 + nt * 8 + g) * 20 + kk2 + tg;
                uint32_t b0 = uB[bo], b1 = uB[bo + 4];
                #pragma unroll
                for (int mt = 0; mt < 4; mt++)
                    mma16(acc[mt][nt], a[mt], b0, b1);
            }
        }
    }
    #undef DOWN_LOAD

    #pragma unroll
    for (int mt = 0; mt < 4; mt++) {
        int rl0 = wm * 64 + mt * 16 + g;
        #pragma unroll
        for (int half = 0; half < 2; half++) {
            int rl = rl0 + half * 8;
            if (ROUTED) {
                int tok = stok[rl];
                if (tok < 0) continue;
                float w = swt[rl];
                float* dst = out + (size_t)tok * H_DIM + n0;
                #pragma unroll
                for (int nt = 0; nt < 4; nt++) {
                    int col = wn * 32 + nt * 8 + tg * 2;
                    atomicAdd(dst + col,     w * acc[mt][nt][half * 2 + 0]);
                    atomicAdd(dst + col + 1, w * acc[mt][nt][half * 2 + 1]);
                }
            } else {
                float* dst = out + (size_t)(m0 + rl) * H_DIM + n0;
                #pragma unroll
                for (int nt = 0; nt < 4; nt++) {
                    int col = wn * 32 + nt * 8 + tg * 2;
                    *(float2*)(dst + col) =
                        make_float2(acc[mt][nt][half * 2 + 0], acc[mt][nt][half * 2 + 1]);
                }
            }
        }
    }
}

// ---------------------------------------------------------------------------
extern "C" void kernel_launch(void* const* d_in, const int* in_sizes, int n_in,
                              void* d_out, int out_size) {
    const float* x  = (const float*)d_in[0];
    const float* gw = (const float*)d_in[1];
    const float* gp = (const float*)d_in[2];
    const float* up = (const float*)d_in[3];
    const float* dp = (const float*)d_in[4];
    const float* sg = (const float*)d_in[5];
    const float* su = (const float*)d_in[6];
    const float* sd = (const float*)d_in[7];
    float* out = (float*)d_out;

    __half *xhP, *w1tP, *w2tP, *wdtP, *sgtP, *sutP, *sdtP, *acthP, *sacthP;
    cudaGetSymbolAddress((void**)&xhP,    g_xh);
    cudaGetSymbolAddress((void**)&w1tP,   g_w1t);
    cudaGetSymbolAddress((void**)&w2tP,   g_w2t);
    cudaGetSymbolAddress((void**)&wdtP,   g_wdt);
    cudaGetSymbolAddress((void**)&sgtP,   g_sgt);
    cudaGetSymbolAddress((void**)&sutP,   g_sut);
    cudaGetSymbolAddress((void**)&sdtP,   g_sdt);
    cudaGetSymbolAddress((void**)&acthP,  g_acth);
    cudaGetSymbolAddress((void**)&sacthP, g_sacth);

    cudaFuncSetAttribute(act_kernel<true>,   cudaFuncAttributeMaxDynamicSharedMemorySize, ACT_SMEM);
    cudaFuncSetAttribute(act_kernel<false>,  cudaFuncAttributeMaxDynamicSharedMemorySize, ACT_SMEM);
    cudaFuncSetAttribute(down_kernel<true>,  cudaFuncAttributeMaxDynamicSharedMemorySize, DOWN_SMEM);
    cudaFuncSetAttribute(down_kernel<false>, cudaFuncAttributeMaxDynamicSharedMemorySize, DOWN_SMEM);

    zero_counts_kernel<<<1, 32>>>();
    gate_topk_kernel<<<T_TOK, 256>>>(x, gw);

    // prepass: fp16 conversion (+ transpose for weights so B is K-contiguous)
    dim3 tb(32, 8);
    f2h_kernel<<<2048, 256>>>((const float4*)x, (uint2*)xhP, (T_TOK * H_DIM) / 4);
    transpose_f2h_kernel<<<dim3(F_DIM / 32, H_DIM / 32, N_EXP), tb>>>(gp, w1tP, H_DIM, F_DIM);
    transpose_f2h_kernel<<<dim3(F_DIM / 32, H_DIM / 32, N_EXP), tb>>>(up, w2tP, H_DIM, F_DIM);
    transpose_f2h_kernel<<<dim3(H_DIM / 32, F_DIM / 32, N_EXP), tb>>>(dp, wdtP, F_DIM, H_DIM);
    transpose_f2h_kernel<<<dim3(SF_DIM / 32, H_DIM / 32, 1), tb>>>(sg, sgtP, H_DIM, SF_DIM);
    transpose_f2h_kernel<<<dim3(SF_DIM / 32, H_DIM / 32, 1), tb>>>(su, sutP, H_DIM, SF_DIM);
    transpose_f2h_kernel<<<dim3(H_DIM / 32, SF_DIM / 32, 1), tb>>>(sd, sdtP, SF_DIM, H_DIM);

    act_kernel<true><<<dim3(F_DIM / 128, T_TOK / 128, N_EXP), 256, ACT_SMEM>>>(xhP, w1tP, w2tP, acthP, F_DIM);
    act_kernel<false><<<dim3(SF_DIM / 128, T_TOK / 128, 1), 256, ACT_SMEM>>>(xhP, sgtP, sutP, sacthP, SF_DIM);

    down_kernel<false><<<dim3(H_DIM / 128, T_TOK / 128, 1), 256, DOWN_SMEM>>>(sacthP, sdtP, out, SF_DIM);
    down_kernel<true><<<dim3(H_DIM / 128, T_TOK / 128, N_EXP), 256, DOWN_SMEM>>>(acthP, wdtP, out, F_DIM);
}

// round 8
// speedup vs baseline: 5.1557x; 1.0458x over previous
#include <cuda_runtime.h>
#include <cuda_fp16.h>
#include <cstdint>

#define T_TOK 2048
#define H_DIM 2048
#define F_DIM 1408
#define SF_DIM 2816
#define N_EXP 8

#define BK 32
#define STAGES 3
#define LDH 40                                   // halves per smem row (80B pitch)
#define ACT_STAGE_H (384 * LDH)                  // A(128) + B1(128) + B2(128) rows
#define DOWN_STAGE_H (256 * LDH)                 // A(128) + B(128)
#define ACT_SMEM (STAGES * ACT_STAGE_H * 2)      // 92160 B
#define DOWN_SMEM (STAGES * DOWN_STAGE_H * 2)    // 61440 B

// ---- scratch (device globals: no allocations allowed) ----
__device__ int    g_count[N_EXP];
__device__ int    g_perm[N_EXP * T_TOK];
__device__ float  g_wgt [N_EXP * T_TOK];
__device__ __half g_xh  [(size_t)T_TOK * H_DIM];           // x fp16 [T][H]
__device__ __half g_w1t [(size_t)N_EXP * F_DIM * H_DIM];   // gate_proj^T [E][F][H]
__device__ __half g_w2t [(size_t)N_EXP * F_DIM * H_DIM];   // up_proj^T   [E][F][H]
__device__ __half g_wdt [(size_t)N_EXP * H_DIM * F_DIM];   // down_proj^T [E][H][F]
__device__ __half g_sgt [(size_t)SF_DIM * H_DIM];          // shared_gate^T [SF][H]
__device__ __half g_sut [(size_t)SF_DIM * H_DIM];          // shared_up^T   [SF][H]
__device__ __half g_sdt [(size_t)H_DIM * SF_DIM];          // shared_down^T [H][SF]
__device__ __half g_acth[(size_t)N_EXP * T_TOK * F_DIM];   // routed act fp16
__device__ __half g_sacth[(size_t)T_TOK * SF_DIM];         // shared act fp16

// ---------------------------------------------------------------------------
__device__ __forceinline__ uint32_t smem_u32(const void* p) {
    uint32_t a;
    asm("{ .reg .u64 t; cvta.to.shared.u64 t, %1; cvt.u32.u64 %0, t; }" : "=r"(a) : "l"(p));
    return a;
}
__device__ __forceinline__ void cpa16s(uint32_t sa, const void* g) {
    asm volatile("cp.async.cg.shared.global [%0], [%1], 16;" :: "r"(sa), "l"(g));
}
#define CP_COMMIT asm volatile("cp.async.commit_group;" ::: "memory")
#define CP_WAIT(n) asm volatile("cp.async.wait_group %0;" :: "n"(n) : "memory")

__device__ __forceinline__ void mma16(float* c, const uint32_t* a, uint32_t b0, uint32_t b1) {
    asm volatile(
        "mma.sync.aligned.m16n8k16.row.col.f32.f16.f16.f32 "
        "{%0,%1,%2,%3}, {%4,%5,%6,%7}, {%8,%9}, {%0,%1,%2,%3};"
        : "+f"(c[0]), "+f"(c[1]), "+f"(c[2]), "+f"(c[3])
        : "r"(a[0]), "r"(a[1]), "r"(a[2]), "r"(a[3]), "r"(b0), "r"(b1));
}
__device__ __forceinline__ void ldsm4(uint32_t* r, uint32_t addr) {
    asm volatile("ldmatrix.sync.aligned.m8n8.x4.shared.b16 {%0,%1,%2,%3}, [%4];"
        : "=r"(r[0]), "=r"(r[1]), "=r"(r[2]), "=r"(r[3]) : "r"(addr));
}

// ---------------------------------------------------------------------------
__global__ void zero_counts_kernel() {
    if (threadIdx.x < N_EXP) g_count[threadIdx.x] = 0;
}

// fp32 -> fp16, no transpose (for x)
__global__ void f2h_kernel(const float4* __restrict__ in, uint2* __restrict__ outp, int n4) {
    int stride = gridDim.x * blockDim.x;
    for (int i = blockIdx.x * blockDim.x + threadIdx.x; i < n4; i += stride) {
        float4 v = in[i];
        __half2 lo = __floats2half2_rn(v.x, v.y);
        __half2 hi = __floats2half2_rn(v.z, v.w);
        outp[i] = make_uint2(*(uint32_t*)&lo, *(uint32_t*)&hi);
    }
}

// fp32 [z][R][C] -> fp16 [z][C][R]
__global__ void transpose_f2h_kernel(const float* __restrict__ in,
                                     __half* __restrict__ outp, int R, int C) {
    __shared__ float t[32][33];
    int tx = threadIdx.x, ty = threadIdx.y;
    int c0 = blockIdx.x * 32, r0 = blockIdx.y * 32;
    size_t zo = (size_t)blockIdx.z * R * C;
    #pragma unroll
    for (int i = 0; i < 4; i++)
        t[ty + i * 8][tx] = in[zo + (size_t)(r0 + ty + i * 8) * C + c0 + tx];
    __syncthreads();
    #pragma unroll
    for (int i = 0; i < 4; i++)
        outp[zo + (size_t)(c0 + ty + i * 8) * R + r0 + tx] = __float2half(t[tx][ty + i * 8]);
}

// ---------------------------------------------------------------------------
__global__ void gate_topk_kernel(const float* __restrict__ x,
                                 const float* __restrict__ gw) {
    __shared__ float xs[H_DIM];
    __shared__ float logits[N_EXP];
    int t = blockIdx.x;
    const float4* xr = (const float4*)(x + (size_t)t * H_DIM);
    for (int i = threadIdx.x; i < H_DIM / 4; i += blockDim.x)
        ((float4*)xs)[i] = xr[i];
    __syncthreads();

    int w = threadIdx.x >> 5, lane = threadIdx.x & 31;
    if (w < N_EXP) {
        const float* gr = gw + (size_t)w * H_DIM;
        float s = 0.f;
        for (int i = lane; i < H_DIM; i += 32) s += xs[i] * gr[i];
        #pragma unroll
        for (int o = 16; o; o >>= 1) s += __shfl_xor_sync(0xffffffffu, s, o);
        if (lane == 0) logits[w] = s;
    }
    __syncthreads();

    if (threadIdx.x == 0) {
        float m = logits[0];
        #pragma unroll
        for (int e = 1; e < N_EXP; e++) m = fmaxf(m, logits[e]);
        float p[N_EXP]; float sum = 0.f;
        #pragma unroll
        for (int e = 0; e < N_EXP; e++) { p[e] = expf(logits[e] - m); sum += p[e]; }
        float inv = 1.f / sum;
        int i0 = 0;
        #pragma unroll
        for (int e = 1; e < N_EXP; e++) if (p[e] > p[i0]) i0 = e;
        int i1 = (i0 == 0) ? 1 : 0;
        #pragma unroll
        for (int e = 0; e < N_EXP; e++) if (e != i0 && p[e] > p[i1]) i1 = e;

        int s0 = atomicAdd(&g_count[i0], 1);
        g_perm[i0 * T_TOK + s0] = t;
        g_wgt [i0 * T_TOK + s0] = p[i0] * inv;
        int s1 = atomicAdd(&g_count[i1], 1);
        g_perm[i1 * T_TOK + s1] = t;
        g_wgt [i1 * T_TOK + s1] = p[i1] * inv;
    }
}

// ---------------------------------------------------------------------------
// act: out_fp16 = silu(A@W1t^T) * (A@W2t^T).  A fp16 [.][KD] k-contig (gathered
// rows), B fp16 [N][KD] k-contig (pre-transposed). block 128x128, warp 64x32.
// Fragment loads via ldmatrix.x4.
template <bool ROUTED>
__global__ void __launch_bounds__(256)
act_kernel(const __half* __restrict__ Ax,
           const __half* __restrict__ B1base,
           const __half* __restrict__ B2base,
           __half* __restrict__ outBase,
           int nld) {    // nld = N total (out pitch); KD = H_DIM
    extern __shared__ __half smem[];
    __shared__ int stok[128];
    const int KD = H_DIM;

    int e = ROUTED ? blockIdx.z : 0;
    int cnt = ROUTED ? g_count[e] : T_TOK;
    int m0 = blockIdx.y * 128;
    if (m0 >= cnt) return;
    int n0 = blockIdx.x * 128;
    int tid = threadIdx.x, wid = tid >> 5, lane = tid & 31;
    int g = lane >> 2, tg = lane & 3;
    int wm = wid & 1, wn = wid >> 1;

    if (tid < 128) {
        int slot = m0 + tid;
        stok[tid] = ROUTED ? ((slot < cnt) ? g_perm[e * T_TOK + slot]
                                           : g_perm[e * T_TOK]) : slot;
    }
    __syncthreads();

    const __half* B1 = B1base + (ROUTED ? (size_t)e * F_DIM * H_DIM : 0);
    const __half* B2 = B2base + (ROUTED ? (size_t)e * F_DIM * H_DIM : 0);
    __half* outE = outBase + (ROUTED ? (size_t)e * T_TOK * nld : 0);
    uint32_t sbase = smem_u32(smem);

    // per-lane ldmatrix row offsets (bytes)
    // A tile (16x16): row = (l&15), col-halves = (l>>4)*8
    uint32_t aOff = (uint32_t)((wm * 64 + (lane & 15)) * 80 + (lane >> 4) * 16);
    // B pair-tile (16 n-rows x k16): row = (l&7)+(l>>4)*8, col-halves = ((l>>3)&1)*8
    uint32_t bOff = (uint32_t)((wn * 32 + (lane & 7) + (lane >> 4) * 8) * 80
                               + ((lane >> 3) & 1) * 16);

    #define ACT_LOAD(st, k0) {                                                  \
        uint32_t base = sbase + (st) * (ACT_STAGE_H * 2);                       \
        _Pragma("unroll")                                                       \
        for (int i = 0; i < 2; i++) {                                           \
            int c = tid + i * 256; int r = c >> 2, j = c & 3;                   \
            cpa16s(base + r * 80 + j * 16,                                      \
                   Ax + (size_t)stok[r] * KD + (k0) + j * 8);                   \
        }                                                                       \
        _Pragma("unroll")                                                       \
        for (int i = 0; i < 2; i++) {                                           \
            int c = tid + i * 256; int r = c >> 2, j = c & 3;                   \
            size_t go = (size_t)(n0 + r) * KD + (k0) + j * 8;                   \
            cpa16s(base + (128 + r) * 80 + j * 16, B1 + go);                    \
            cpa16s(base + (256 + r) * 80 + j * 16, B2 + go);                    \
        }                                                                       \
        CP_COMMIT;                                                              \
    }

    float acc1[4][4][4], acc2[4][4][4];
    #pragma unroll
    for (int mt = 0; mt < 4; mt++)
        #pragma unroll
        for (int nt = 0; nt < 4; nt++)
            #pragma unroll
            for (int q = 0; q < 4; q++) { acc1[mt][nt][q] = 0.f; acc2[mt][nt][q] = 0.f; }

    const int NIT = KD / BK;   // 64
    ACT_LOAD(0, 0);
    ACT_LOAD(1, BK);

    for (int it = 0; it < NIT; ++it) {
        if (it + 1 < NIT) CP_WAIT(1); else CP_WAIT(0);
        __syncthreads();
        if (it + 2 < NIT) ACT_LOAD((it + 2) % STAGES, (it + 2) * BK);

        uint32_t stg = sbase + (it % STAGES) * (ACT_STAGE_H * 2);
        uint32_t aB = stg + aOff;
        uint32_t b1B = stg + 128 * 80 + bOff;
        uint32_t b2B = stg + 256 * 80 + bOff;

        #pragma unroll
        for (int s = 0; s < 2; s++) {   // two k16 steps
            uint32_t a[4][4];
            #pragma unroll
            for (int mt = 0; mt < 4; mt++)
                ldsm4(a[mt], aB + mt * (16 * 80) + s * 32);
            #pragma unroll
            for (int p = 0; p < 2; p++) {   // nt pairs {0,1},{2,3}
                uint32_t rb1[4], rb2[4];
                ldsm4(rb1, b1B + p * (16 * 80) + s * 32);
                ldsm4(rb2, b2B + p * (16 * 80) + s * 32);
                #pragma unroll
                for (int mt = 0; mt < 4; mt++) {
                    mma16(acc1[mt][2 * p],     a[mt], rb1[0], rb1[1]);
                    mma16(acc1[mt][2 * p + 1], a[mt], rb1[2], rb1[3]);
                    mma16(acc2[mt][2 * p],     a[mt], rb2[0], rb2[1]);
                    mma16(acc2[mt][2 * p + 1], a[mt], rb2[2], rb2[3]);
                }
            }
        }
    }
    #undef ACT_LOAD

    // epilogue: silu(g)*u -> fp16
    #pragma unroll
    for (int mt = 0; mt < 4; mt++) {
        #pragma unroll
        for (int nt = 0; nt < 4; nt++) {
            float v[4];
            #pragma unroll
            for (int q = 0; q < 4; q++) {
                float gv = acc1[mt][nt][q], uv = acc2[mt][nt][q];
                v[q] = (gv / (1.f + __expf(-gv))) * uv;
            }
            __half2 lo = __floats2half2_rn(v[0], v[1]);
            __half2 hi = __floats2half2_rn(v[2], v[3]);
            int row = m0 + wm * 64 + mt * 16 + g;
            int col = n0 + wn * 32 + nt * 8 + tg * 2;
            *(uint32_t*)(outE + (size_t)row * nld + col)       = *(uint32_t*)&lo;
            *(uint32_t*)(outE + (size_t)(row + 8) * nld + col) = *(uint32_t*)&hi;
        }
    }
}

// ---------------------------------------------------------------------------
// down: C = A @ Wd (B pre-transposed [H][KD] k-contig). block 128x128, warp 64x32.
template <bool ROUTED>
__global__ void __launch_bounds__(256, 2)
down_kernel(const __half* __restrict__ Abase,
            const __half* __restrict__ Bbase,
            float* __restrict__ out,
            int KD) {
    extern __shared__ __half smem[];
    __shared__ int   stok[128];
    __shared__ float swt[128];

    int e = ROUTED ? blockIdx.z : 0;
    int cnt = ROUTED ? g_count[e] : T_TOK;
    int m0 = blockIdx.y * 128;
    if (m0 >= cnt) return;
    int n0 = blockIdx.x * 128;
    int tid = threadIdx.x, wid = tid >> 5, lane = tid & 31;
    int g = lane >> 2, tg = lane & 3;
    int wm = wid & 1, wn = wid >> 1;

    if (ROUTED && tid < 128) {
        int slot = m0 + tid;
        bool v = slot < cnt;
        stok[tid] = v ? g_perm[e * T_TOK + slot] : -1;
        swt[tid]  = v ? g_wgt [e * T_TOK + slot] : 0.f;
    }
    __syncthreads();

    const __half* A = Abase + (ROUTED ? (size_t)e * T_TOK * KD : 0);
    const __half* B = Bbase + (ROUTED ? (size_t)e * H_DIM * KD : 0);
    uint32_t sbase = smem_u32(smem);

    uint32_t aOff = (uint32_t)((wm * 64 + (lane & 15)) * 80 + (lane >> 4) * 16);
    uint32_t bOff = (uint32_t)((wn * 32 + (lane & 7) + (lane >> 4) * 8) * 80
                               + ((lane >> 3) & 1) * 16);

    #define DOWN_LOAD(st, k0) {                                                 \
        uint32_t base = sbase + (st) * (DOWN_STAGE_H * 2);                      \
        _Pragma("unroll")                                                       \
        for (int i = 0; i < 2; i++) {                                           \
            int c = tid + i * 256; int r = c >> 2, j = c & 3;                   \
            cpa16s(base + r * 80 + j * 16,                                      \
                   A + (size_t)(m0 + r) * KD + (k0) + j * 8);                   \
        }                                                                       \
        _Pragma("unroll")                                                       \
        for (int i = 0; i < 2; i++) {                                           \
            int c = tid + i * 256; int r = c >> 2, j = c & 3;                   \
            cpa16s(base + (128 + r) * 80 + j * 16,                              \
                   B + (size_t)(n0 + r) * KD + (k0) + j * 8);                   \
        }                                                                       \
        CP_COMMIT;                                                              \
    }

    float acc[4][4][4];
    #pragma unroll
    for (int mt = 0; mt < 4; mt++)
        #pragma unroll
        for (int nt = 0; nt < 4; nt++)
            #pragma unroll
            for (int q = 0; q < 4; q++) acc[mt][nt][q] = 0.f;

    const int NIT = KD / BK;
    DOWN_LOAD(0, 0);
    DOWN_LOAD(1, BK);

    for (int it = 0; it < NIT; ++it) {
        if (it + 1 < NIT) CP_WAIT(1); else CP_WAIT(0);
        __syncthreads();
        if (it + 2 < NIT) DOWN_LOAD((it + 2) % STAGES, (it + 2) * BK);

        uint32_t stg = sbase + (it % STAGES) * (DOWN_STAGE_H * 2);
        uint32_t aB = stg + aOff;
        uint32_t bB = stg + 128 * 80 + bOff;

        #pragma unroll
        for (int s = 0; s < 2; s++) {
            uint32_t a[4][4];
            #pragma unroll
            for (int mt = 0; mt < 4; mt++)
                ldsm4(a[mt], aB + mt * (16 * 80) + s * 32);
            #pragma unroll
            for (int p = 0; p < 2; p++) {
                uint32_t rb[4];
                ldsm4(rb, bB + p * (16 * 80) + s * 32);
                #pragma unroll
                for (int mt = 0; mt < 4; mt++) {
                    mma16(acc[mt][2 * p],     a[mt], rb[0], rb[1]);
                    mma16(acc[mt][2 * p + 1], a[mt], rb[2], rb[3]);
                }
            }
        }
    }
    #undef DOWN_LOAD

    #pragma unroll
    for (int mt = 0; mt < 4; mt++) {
        int rl0 = wm * 64 + mt * 16 + g;
        #pragma unroll
        for (int half = 0; half < 2; half++) {
            int rl = rl0 + half * 8;
            if (ROUTED) {
                int tok = stok[rl];
                if (tok < 0) continue;
                float w = swt[rl];
                float* dst = out + (size_t)tok * H_DIM + n0;
                #pragma unroll
                for (int nt = 0; nt < 4; nt++) {
                    int col = wn * 32 + nt * 8 + tg * 2;
                    atomicAdd(dst + col,     w * acc[mt][nt][half * 2 + 0]);
                    atomicAdd(dst + col + 1, w * acc[mt][nt][half * 2 + 1]);
                }
            } else {
                float* dst = out + (size_t)(m0 + rl) * H_DIM + n0;
                #pragma unroll
                for (int nt = 0; nt < 4; nt++) {
                    int col = wn * 32 + nt * 8 + tg * 2;
                    *(float2*)(dst + col) =
                        make_float2(acc[mt][nt][half * 2 + 0], acc[mt][nt][half * 2 + 1]);
                }
            }
        }
    }
}

// ---------------------------------------------------------------------------
extern "C" void kernel_launch(void* const* d_in, const int* in_sizes, int n_in,
                              void* d_out, int out_size) {
    const float* x  = (const float*)d_in[0];
    const float* gw = (const float*)d_in[1];
    const float* gp = (const float*)d_in[2];
    const float* up = (const float*)d_in[3];
    const float* dp = (const float*)d_in[4];
    const float* sg = (const float*)d_in[5];
    const float* su = (const float*)d_in[6];
    const float* sd = (const float*)d_in[7];
    float* out = (float*)d_out;

    __half *xhP, *w1tP, *w2tP, *wdtP, *sgtP, *sutP, *sdtP, *acthP, *sacthP;
    cudaGetSymbolAddress((void**)&xhP,    g_xh);
    cudaGetSymbolAddress((void**)&w1tP,   g_w1t);
    cudaGetSymbolAddress((void**)&w2tP,   g_w2t);
    cudaGetSymbolAddress((void**)&wdtP,   g_wdt);
    cudaGetSymbolAddress((void**)&sgtP,   g_sgt);
    cudaGetSymbolAddress((void**)&sutP,   g_sut);
    cudaGetSymbolAddress((void**)&sdtP,   g_sdt);
    cudaGetSymbolAddress((void**)&acthP,  g_acth);
    cudaGetSymbolAddress((void**)&sacthP, g_sacth);

    cudaFuncSetAttribute(act_kernel<true>,   cudaFuncAttributeMaxDynamicSharedMemorySize, ACT_SMEM);
    cudaFuncSetAttribute(act_kernel<false>,  cudaFuncAttributeMaxDynamicSharedMemorySize, ACT_SMEM);
    cudaFuncSetAttribute(down_kernel<true>,  cudaFuncAttributeMaxDynamicSharedMemorySize, DOWN_SMEM);
    cudaFuncSetAttribute(down_kernel<false>, cudaFuncAttributeMaxDynamicSharedMemorySize, DOWN_SMEM);

    zero_counts_kernel<<<1, 32>>>();
    gate_topk_kernel<<<T_TOK, 256>>>(x, gw);

    // prepass: fp16 conversion (+ transpose for weights so B is K-contiguous)
    dim3 tb(32, 8);
    f2h_kernel<<<2048, 256>>>((const float4*)x, (uint2*)xhP, (T_TOK * H_DIM) / 4);
    transpose_f2h_kernel<<<dim3(F_DIM / 32, H_DIM / 32, N_EXP), tb>>>(gp, w1tP, H_DIM, F_DIM);
    transpose_f2h_kernel<<<dim3(F_DIM / 32, H_DIM / 32, N_EXP), tb>>>(up, w2tP, H_DIM, F_DIM);
    transpose_f2h_kernel<<<dim3(H_DIM / 32, F_DIM / 32, N_EXP), tb>>>(dp, wdtP, F_DIM, H_DIM);
    transpose_f2h_kernel<<<dim3(SF_DIM / 32, H_DIM / 32, 1), tb>>>(sg, sgtP, H_DIM, SF_DIM);
    transpose_f2h_kernel<<<dim3(SF_DIM / 32, H_DIM / 32, 1), tb>>>(su, sutP, H_DIM, SF_DIM);
    transpose_f2h_kernel<<<dim3(H_DIM / 32, SF_DIM / 32, 1), tb>>>(sd, sdtP, SF_DIM, H_DIM);

    act_kernel<true><<<dim3(F_DIM / 128, T_TOK / 128, N_EXP), 256, ACT_SMEM>>>(xhP, w1tP, w2tP, acthP, F_DIM);
    act_kernel<false><<<dim3(SF_DIM / 128, T_TOK / 128, 1), 256, ACT_SMEM>>>(xhP, sgtP, sutP, sacthP, SF_DIM);

    down_kernel<false><<<dim3(H_DIM / 128, T_TOK / 128, 1), 256, DOWN_SMEM>>>(sacthP, sdtP, out, SF_DIM);
    down_kernel<true><<<dim3(H_DIM / 128, T_TOK / 128, N_EXP), 256, DOWN_SMEM>>>(acthP, wdtP, out, F_DIM);
}

// round 10
// speedup vs baseline: 5.3854x; 1.0446x over previous
#include <cuda_runtime.h>
#include <cuda_fp16.h>
#include <cstdint>

#define T_TOK 2048
#define H_DIM 2048
#define F_DIM 1408
#define SF_DIM 2816
#define N_EXP 8

#define BK 32
#define STAGES 3
#define ACT_STAGE_H (384 * 40)                   // A(128) + B1(128) + B2(128) rows, 80B pitch
#define DOWN_STAGE_H (256 * 40)                  // A(128) + B(128)
#define ACT_SMEM (STAGES * ACT_STAGE_H * 2)      // 92160 B
#define DOWN_SMEM (STAGES * DOWN_STAGE_H * 2)    // 61440 B

// ---- scratch (device globals: no allocations allowed) ----
__device__ int    g_count[N_EXP];
__device__ int    g_perm[N_EXP * T_TOK];
__device__ int    g_slot[2 * T_TOK];                       // token -> absolute slot (e*T_TOK+s)
__device__ float  g_tokw[2 * T_TOK];                       // token -> combine weight
__device__ __half g_xh  [(size_t)T_TOK * H_DIM];           // x fp16 [T][H]
__device__ __half g_w1t [(size_t)N_EXP * F_DIM * H_DIM];   // gate_proj^T [E][F][H]
__device__ __half g_w2t [(size_t)N_EXP * F_DIM * H_DIM];   // up_proj^T   [E][F][H]
__device__ __half g_wdt [(size_t)N_EXP * H_DIM * F_DIM];   // down_proj^T [E][H][F]
__device__ __half g_sgt [(size_t)SF_DIM * H_DIM];          // shared_gate^T [SF][H]
__device__ __half g_sut [(size_t)SF_DIM * H_DIM];          // shared_up^T   [SF][H]
__device__ __half g_sdt [(size_t)H_DIM * SF_DIM];          // shared_down^T [H][SF]
__device__ __half g_acth[(size_t)N_EXP * T_TOK * F_DIM];   // routed act fp16 (slot rows)
__device__ __half g_sacth[(size_t)T_TOK * SF_DIM];         // shared act fp16
__device__ float  g_dout[(size_t)N_EXP * T_TOK * H_DIM];   // routed down out (slot rows)

// ---------------------------------------------------------------------------
__device__ __forceinline__ uint32_t smem_u32(const void* p) {
    uint32_t a;
    asm("{ .reg .u64 t; cvta.to.shared.u64 t, %1; cvt.u32.u64 %0, t; }" : "=r"(a) : "l"(p));
    return a;
}
__device__ __forceinline__ void cpa16s(uint32_t sa, const void* g) {
    asm volatile("cp.async.cg.shared.global [%0], [%1], 16;" :: "r"(sa), "l"(g));
}
#define CP_COMMIT asm volatile("cp.async.commit_group;" ::: "memory")
#define CP_WAIT(n) asm volatile("cp.async.wait_group %0;" :: "n"(n) : "memory")

__device__ __forceinline__ void mma16(float* c, const uint32_t* a, uint32_t b0, uint32_t b1) {
    asm volatile(
        "mma.sync.aligned.m16n8k16.row.col.f32.f16.f16.f32 "
        "{%0,%1,%2,%3}, {%4,%5,%6,%7}, {%8,%9}, {%0,%1,%2,%3};"
        : "+f"(c[0]), "+f"(c[1]), "+f"(c[2]), "+f"(c[3])
        : "r"(a[0]), "r"(a[1]), "r"(a[2]), "r"(a[3]), "r"(b0), "r"(b1));
}
__device__ __forceinline__ void ldsm4(uint32_t* r, uint32_t addr) {
    asm volatile("ldmatrix.sync.aligned.m8n8.x4.shared.b16 {%0,%1,%2,%3}, [%4];"
        : "=r"(r[0]), "=r"(r[1]), "=r"(r[2]), "=r"(r[3]) : "r"(addr));
}

// ---------------------------------------------------------------------------
__global__ void zero_counts_kernel() {
    if (threadIdx.x < N_EXP) g_count[threadIdx.x] = 0;
}

// fp32 -> fp16, no transpose (for x)
__global__ void f2h_kernel(const float4* __restrict__ in, uint2* __restrict__ outp, int n4) {
    int stride = gridDim.x * blockDim.x;
    for (int i = blockIdx.x * blockDim.x + threadIdx.x; i < n4; i += stride) {
        float4 v = in[i];
        __half2 lo = __floats2half2_rn(v.x, v.y);
        __half2 hi = __floats2half2_rn(v.z, v.w);
        outp[i] = make_uint2(*(uint32_t*)&lo, *(uint32_t*)&hi);
    }
}

// fp32 [z][R][C] -> fp16 [z][C][R]   (half2-vectorized writes, in-bounds)
__global__ void transpose_f2h_kernel(const float* __restrict__ in,
                                     __half* __restrict__ outp, int R, int C) {
    __shared__ float t[32][33];
    int tx = threadIdx.x, ty = threadIdx.y;   // (32, 8)
    int c0 = blockIdx.x * 32, r0 = blockIdx.y * 32;
    size_t zo = (size_t)blockIdx.z * R * C;
    #pragma unroll
    for (int i = 0; i < 4; i++)
        t[ty + i * 8][tx] = in[zo + (size_t)(r0 + ty + i * 8) * C + c0 + tx];
    __syncthreads();
    // each thread: rows 2*(tx&15), 2*(tx&15)+1 ; cols ty + ((tx>>4)<<3) + i*16
    int r = (tx & 15) * 2;
    #pragma unroll
    for (int i = 0; i < 2; i++) {
        int c = ty + ((tx >> 4) << 3) + i * 16;
        __half2 v = __floats2half2_rn(t[r][c], t[r + 1][c]);
        *(__half2*)(outp + zo + (size_t)(c0 + c) * R + r0 + r) = v;
    }
}

// ---------------------------------------------------------------------------
__global__ void gate_topk_kernel(const float* __restrict__ x,
                                 const float* __restrict__ gw) {
    __shared__ float xs[H_DIM];
    __shared__ float logits[N_EXP];
    int t = blockIdx.x;
    const float4* xr = (const float4*)(x + (size_t)t * H_DIM);
    for (int i = threadIdx.x; i < H_DIM / 4; i += blockDim.x)
        ((float4*)xs)[i] = xr[i];
    __syncthreads();

    int w = threadIdx.x >> 5, lane = threadIdx.x & 31;
    if (w < N_EXP) {
        const float* gr = gw + (size_t)w * H_DIM;
        float s = 0.f;
        for (int i = lane; i < H_DIM; i += 32) s += xs[i] * gr[i];
        #pragma unroll
        for (int o = 16; o; o >>= 1) s += __shfl_xor_sync(0xffffffffu, s, o);
        if (lane == 0) logits[w] = s;
    }
    __syncthreads();

    if (threadIdx.x == 0) {
        float m = logits[0];
        #pragma unroll
        for (int e = 1; e < N_EXP; e++) m = fmaxf(m, logits[e]);
        float p[N_EXP]; float sum = 0.f;
        #pragma unroll
        for (int e = 0; e < N_EXP; e++) { p[e] = expf(logits[e] - m); sum += p[e]; }
        float inv = 1.f / sum;
        int i0 = 0;
        #pragma unroll
        for (int e = 1; e < N_EXP; e++) if (p[e] > p[i0]) i0 = e;
        int i1 = (i0 == 0) ? 1 : 0;
        #pragma unroll
        for (int e = 0; e < N_EXP; e++) if (e != i0 && p[e] > p[i1]) i1 = e;

        int s0 = atomicAdd(&g_count[i0], 1);
        g_perm[i0 * T_TOK + s0] = t;
        g_slot[2 * t]     = i0 * T_TOK + s0;
        g_tokw[2 * t]     = p[i0] * inv;
        int s1 = atomicAdd(&g_count[i1], 1);
        g_perm[i1 * T_TOK + s1] = t;
        g_slot[2 * t + 1] = i1 * T_TOK + s1;
        g_tokw[2 * t + 1] = p[i1] * inv;
    }
}

// ---------------------------------------------------------------------------
// out[t] += w0 * dout[slot0] + w1 * dout[slot1]
__global__ void combine_kernel(float* __restrict__ out) {
    int t = blockIdx.x;
    int s0 = g_slot[2 * t], s1 = g_slot[2 * t + 1];
    float w0 = g_tokw[2 * t], w1 = g_tokw[2 * t + 1];
    const float4* d0 = (const float4*)(g_dout + (size_t)s0 * H_DIM);
    const float4* d1 = (const float4*)(g_dout + (size_t)s1 * H_DIM);
    float4* o = (float4*)(out + (size_t)t * H_DIM);
    for (int i = threadIdx.x; i < H_DIM / 4; i += blockDim.x) {
        float4 a = o[i], b = d0[i], c = d1[i];
        a.x += w0 * b.x + w1 * c.x;
        a.y += w0 * b.y + w1 * c.y;
        a.z += w0 * b.z + w1 * c.z;
        a.w += w0 * b.w + w1 * c.w;
        o[i] = a;
    }
}

// ---------------------------------------------------------------------------
// act: out_fp16 = silu(A@W1t^T) * (A@W2t^T). 512 threads, block 128x128,
// warp tile 32x32 (warps 4m x 4n), ldmatrix fragment loads.
template <bool ROUTED>
__global__ void __launch_bounds__(512)
act_kernel(const __half* __restrict__ Ax,
           const __half* __restrict__ B1base,
           const __half* __restrict__ B2base,
           __half* __restrict__ outBase,
           int nld) {    // nld = N total (out pitch); KD = H_DIM
    extern __shared__ __half smem[];
    __shared__ int stok[128];
    const int KD = H_DIM;

    int e = ROUTED ? blockIdx.z : 0;
    int cnt = ROUTED ? g_count[e] : T_TOK;
    int m0 = blockIdx.y * 128;
    if (m0 >= cnt) return;
    int n0 = blockIdx.x * 128;
    int tid = threadIdx.x, wid = tid >> 5, lane = tid & 31;
    int g = lane >> 2, tg = lane & 3;
    int wm = wid & 3, wn = wid >> 2;     // 4 x 4 warps, 32x32 tiles

    if (tid < 128) {
        int slot = m0 + tid;
        stok[tid] = ROUTED ? ((slot < cnt) ? g_perm[e * T_TOK + slot]
                                           : g_perm[e * T_TOK]) : slot;
    }
    __syncthreads();

    const __half* B1 = B1base + (ROUTED ? (size_t)e * F_DIM * H_DIM : 0);
    const __half* B2 = B2base + (ROUTED ? (size_t)e * F_DIM * H_DIM : 0);
    __half* outE = outBase + (ROUTED ? (size_t)e * T_TOK * nld : 0);
    uint32_t sbase = smem_u32(smem);

    uint32_t aOff = (uint32_t)((wm * 32 + (lane & 15)) * 80 + (lane >> 4) * 16);
    uint32_t bOff = (uint32_t)((wn * 32 + (lane & 7) + (lane >> 4) * 8) * 80
                               + ((lane >> 3) & 1) * 16);

    // per stage: A rows [0,128), B1 rows [128,256), B2 rows [256,384); 80B pitch
    #define ACT_LOAD(st, k0) {                                                  \
        uint32_t base = sbase + (st) * (ACT_STAGE_H * 2);                       \
        { int r = tid >> 2, j = tid & 3;                                        \
          cpa16s(base + r * 80 + j * 16,                                        \
                 Ax + (size_t)stok[r] * KD + (k0) + j * 8);                     \
          size_t go = (size_t)(n0 + r) * KD + (k0) + j * 8;                     \
          cpa16s(base + (128 + r) * 80 + j * 16, B1 + go);                      \
          cpa16s(base + (256 + r) * 80 + j * 16, B2 + go); }                    \
        CP_COMMIT;                                                              \
    }

    float acc1[2][4][4], acc2[2][4][4];
    #pragma unroll
    for (int mt = 0; mt < 2; mt++)
        #pragma unroll
        for (int nt = 0; nt < 4; nt++)
            #pragma unroll
            for (int q = 0; q < 4; q++) { acc1[mt][nt][q] = 0.f; acc2[mt][nt][q] = 0.f; }

    const int NIT = KD / BK;   // 64
    ACT_LOAD(0, 0);
    ACT_LOAD(1, BK);

    for (int it = 0; it < NIT; ++it) {
        if (it + 1 < NIT) CP_WAIT(1); else CP_WAIT(0);
        __syncthreads();
        if (it + 2 < NIT) ACT_LOAD((it + 2) % STAGES, (it + 2) * BK);

        uint32_t stg = sbase + (it % STAGES) * (ACT_STAGE_H * 2);
        uint32_t aB = stg + aOff;
        uint32_t b1B = stg + 128 * 80 + bOff;
        uint32_t b2B = stg + 256 * 80 + bOff;

        #pragma unroll
        for (int s = 0; s < 2; s++) {   // two k16 steps
            uint32_t a[2][4];
            #pragma unroll
            for (int mt = 0; mt < 2; mt++)
                ldsm4(a[mt], aB + mt * (16 * 80) + s * 32);
            #pragma unroll
            for (int p = 0; p < 2; p++) {   // nt pairs {0,1},{2,3}
                uint32_t rb1[4], rb2[4];
                ldsm4(rb1, b1B + p * (16 * 80) + s * 32);
                ldsm4(rb2, b2B + p * (16 * 80) + s * 32);
                #pragma unroll
                for (int mt = 0; mt < 2; mt++) {
                    mma16(acc1[mt][2 * p],     a[mt], rb1[0], rb1[1]);
                    mma16(acc1[mt][2 * p + 1], a[mt], rb1[2], rb1[3]);
                    mma16(acc2[mt][2 * p],     a[mt], rb2[0], rb2[1]);
                    mma16(acc2[mt][2 * p + 1], a[mt], rb2[2], rb2[3]);
                }
            }
        }
    }
    #undef ACT_LOAD

    // epilogue: silu(g)*u -> fp16
    #pragma unroll
    for (int mt = 0; mt < 2; mt++) {
        #pragma unroll
        for (int nt = 0; nt < 4; nt++) {
            float v[4];
            #pragma unroll
            for (int q = 0; q < 4; q++) {
                float gv = acc1[mt][nt][q], uv = acc2[mt][nt][q];
                v[q] = (gv / (1.f + __expf(-gv))) * uv;
            }
            __half2 lo = __floats2half2_rn(v[0], v[1]);
            __half2 hi = __floats2half2_rn(v[2], v[3]);
            int row = m0 + wm * 32 + mt * 16 + g;
            int col = n0 + wn * 32 + nt * 8 + tg * 2;
            *(uint32_t*)(outE + (size_t)row * nld + col)       = *(uint32_t*)&lo;
            *(uint32_t*)(outE + (size_t)(row + 8) * nld + col) = *(uint32_t*)&hi;
        }
    }
}

// ---------------------------------------------------------------------------
// down: C = A @ Wd (B pre-transposed [H][KD] k-contig). 512 threads, block
// 128x128, warp tile 32x32. Plain fp32 stores (slot rows for ROUTED).
template <bool ROUTED>
__global__ void __launch_bounds__(512)
down_kernel(const __half* __restrict__ Abase,
            const __half* __restrict__ Bbase,
            float* __restrict__ out,
            int KD) {
    extern __shared__ __half smem[];

    int e = ROUTED ? blockIdx.z : 0;
    int cnt = ROUTED ? g_count[e] : T_TOK;
    int m0 = blockIdx.y * 128;
    if (m0 >= cnt) return;
    int n0 = blockIdx.x * 128;
    int tid = threadIdx.x, wid = tid >> 5, lane = tid & 31;
    int g = lane >> 2, tg = lane & 3;
    int wm = wid & 3, wn = wid >> 2;

    const __half* A = Abase + (ROUTED ? (size_t)e * T_TOK * KD : 0);
    const __half* B = Bbase + (ROUTED ? (size_t)e * H_DIM * KD : 0);
    float* outE = out + (ROUTED ? (size_t)e * T_TOK * H_DIM : 0);
    uint32_t sbase = smem_u32(smem);

    uint32_t aOff = (uint32_t)((wm * 32 + (lane & 15)) * 80 + (lane >> 4) * 16);
    uint32_t bOff = (uint32_t)((wn * 32 + (lane & 7) + (lane >> 4) * 8) * 80
                               + ((lane >> 3) & 1) * 16);

    #define DOWN_LOAD(st, k0) {                                                 \
        uint32_t base = sbase + (st) * (DOWN_STAGE_H * 2);                      \
        { int r = tid >> 2, j = tid & 3;                                        \
          cpa16s(base + r * 80 + j * 16,                                        \
                 A + (size_t)(m0 + r) * KD + (k0) + j * 8);                     \
          cpa16s(base + (128 + r) * 80 + j * 16,                                \
                 B + (size_t)(n0 + r) * KD + (k0) + j * 8); }                   \
        CP_COMMIT;                                                              \
    }

    float acc[2][4][4];
    #pragma unroll
    for (int mt = 0; mt < 2; mt++)
        #pragma unroll
        for (int nt = 0; nt < 4; nt++)
            #pragma unroll
            for (int q = 0; q < 4; q++) acc[mt][nt][q] = 0.f;

    const int NIT = KD / BK;
    DOWN_LOAD(0, 0);
    DOWN_LOAD(1, BK);

    for (int it = 0; it < NIT; ++it) {
        if (it + 1 < NIT) CP_WAIT(1); else CP_WAIT(0);
        __syncthreads();
        if (it + 2 < NIT) DOWN_LOAD((it + 2) % STAGES, (it + 2) * BK);

        uint32_t stg = sbase + (it % STAGES) * (DOWN_STAGE_H * 2);
        uint32_t aB = stg + aOff;
        uint32_t bB = stg + 128 * 80 + bOff;

        #pragma unroll
        for (int s = 0; s < 2; s++) {
            uint32_t a[2][4];
            #pragma unroll
            for (int mt = 0; mt < 2; mt++)
                ldsm4(a[mt], aB + mt * (16 * 80) + s * 32);
            #pragma unroll
            for (int p = 0; p < 2; p++) {
                uint32_t rb[4];
                ldsm4(rb, bB + p * (16 * 80) + s * 32);
                #pragma unroll
                for (int mt = 0; mt < 2; mt++) {
                    mma16(acc[mt][2 * p],     a[mt], rb[0], rb[1]);
                    mma16(acc[mt][2 * p + 1], a[mt], rb[2], rb[3]);
                }
            }
        }
    }
    #undef DOWN_LOAD

    #pragma unroll
    for (int mt = 0; mt < 2; mt++) {
        #pragma unroll
        for (int half = 0; half < 2; half++) {
            int rl = wm * 32 + mt * 16 + g + half * 8;
            float* dst = outE + (size_t)(m0 + rl) * H_DIM + n0;
            #pragma unroll
            for (int nt = 0; nt < 4; nt++) {
                int col = wn * 32 + nt * 8 + tg * 2;
                *(float2*)(dst + col) =
                    make_float2(acc[mt][nt][half * 2 + 0], acc[mt][nt][half * 2 + 1]);
            }
        }
    }
}

// ---------------------------------------------------------------------------
extern "C" void kernel_launch(void* const* d_in, const int* in_sizes, int n_in,
                              void* d_out, int out_size) {
    const float* x  = (const float*)d_in[0];
    const float* gw = (const float*)d_in[1];
    const float* gp = (const float*)d_in[2];
    const float* up = (const float*)d_in[3];
    const float* dp = (const float*)d_in[4];
    const float* sg = (const float*)d_in[5];
    const float* su = (const float*)d_in[6];
    const float* sd = (const float*)d_in[7];
    float* out = (float*)d_out;

    __half *xhP, *w1tP, *w2tP, *wdtP, *sgtP, *sutP, *sdtP, *acthP, *sacthP;
    float* doutP;
    cudaGetSymbolAddress((void**)&xhP,    g_xh);
    cudaGetSymbolAddress((void**)&w1tP,   g_w1t);
    cudaGetSymbolAddress((void**)&w2tP,   g_w2t);
    cudaGetSymbolAddress((void**)&wdtP,   g_wdt);
    cudaGetSymbolAddress((void**)&sgtP,   g_sgt);
    cudaGetSymbolAddress((void**)&sutP,   g_sut);
    cudaGetSymbolAddress((void**)&sdtP,   g_sdt);
    cudaGetSymbolAddress((void**)&acthP,  g_acth);
    cudaGetSymbolAddress((void**)&sacthP, g_sacth);
    cudaGetSymbolAddress((void**)&doutP,  g_dout);

    cudaFuncSetAttribute(act_kernel<true>,   cudaFuncAttributeMaxDynamicSharedMemorySize, ACT_SMEM);
    cudaFuncSetAttribute(act_kernel<false>,  cudaFuncAttributeMaxDynamicSharedMemorySize, ACT_SMEM);
    cudaFuncSetAttribute(down_kernel<true>,  cudaFuncAttributeMaxDynamicSharedMemorySize, DOWN_SMEM);
    cudaFuncSetAttribute(down_kernel<false>, cudaFuncAttributeMaxDynamicSharedMemorySize, DOWN_SMEM);

    zero_counts_kernel<<<1, 32>>>();
    gate_topk_kernel<<<T_TOK, 256>>>(x, gw);

    // prepass: fp16 conversion (+ transpose for weights so B is K-contiguous)
    dim3 tb(32, 8);
    f2h_kernel<<<2048, 256>>>((const float4*)x, (uint2*)xhP, (T_TOK * H_DIM) / 4);
    transpose_f2h_kernel<<<dim3(F_DIM / 32, H_DIM / 32, N_EXP), tb>>>(gp, w1tP, H_DIM, F_DIM);
    transpose_f2h_kernel<<<dim3(F_DIM / 32, H_DIM / 32, N_EXP), tb>>>(up, w2tP, H_DIM, F_DIM);
    transpose_f2h_kernel<<<dim3(H_DIM / 32, F_DIM / 32, N_EXP), tb>>>(dp, wdtP, F_DIM, H_DIM);
    transpose_f2h_kernel<<<dim3(SF_DIM / 32, H_DIM / 32, 1), tb>>>(sg, sgtP, H_DIM, SF_DIM);
    transpose_f2h_kernel<<<dim3(SF_DIM / 32, H_DIM / 32, 1), tb>>>(su, sutP, H_DIM, SF_DIM);
    transpose_f2h_kernel<<<dim3(H_DIM / 32, SF_DIM / 32, 1), tb>>>(sd, sdtP, SF_DIM, H_DIM);

    act_kernel<true><<<dim3(F_DIM / 128, T_TOK / 128, N_EXP), 512, ACT_SMEM>>>(xhP, w1tP, w2tP, acthP, F_DIM);
    act_kernel<false><<<dim3(SF_DIM / 128, T_TOK / 128, 1), 512, ACT_SMEM>>>(xhP, sgtP, sutP, sacthP, SF_DIM);

    // shared down writes out directly; routed down writes slot rows; combine adds
    down_kernel<false><<<dim3(H_DIM / 128, T_TOK / 128, 1), 512, DOWN_SMEM>>>(sacthP, sdtP, out, SF_DIM);
    down_kernel<true><<<dim3(H_DIM / 128, T_TOK / 128, N_EXP), 512, DOWN_SMEM>>>(acthP, wdtP, doutP, F_DIM);
    combine_kernel<<<T_TOK, 256>>>(out);
}

// round 11
// speedup vs baseline: 6.1830x; 1.1481x over previous
#include <cuda_runtime.h>
#include <cuda_fp16.h>
#include <cstdint>

#define T_TOK 2048
#define H_DIM 2048
#define F_DIM 1408
#define SF_DIM 2816
#define N_EXP 8

#define BK 32
#define STAGES 3
#define ACT_STAGE_H (384 * 40)                   // A(128) + B1(128) + B2(128) rows, 80B pitch
#define DOWN_STAGE_H (256 * 40)                  // A(128) + B(128)
#define ACT_SMEM (STAGES * ACT_STAGE_H * 2)      // 92160 B
#define DOWN_SMEM (STAGES * DOWN_STAGE_H * 2)    // 61440 B

// ---- scratch (device globals: no allocations allowed) ----
__device__ int    g_count[N_EXP];
__device__ int    g_perm[N_EXP * T_TOK];
__device__ int    g_slot[2 * T_TOK];                       // token -> absolute slot (e*T_TOK+s)
__device__ float  g_tokw[2 * T_TOK];                       // token -> combine weight
__device__ __half g_xh  [(size_t)T_TOK * H_DIM];           // x fp16 [T][H]
__device__ __half g_w1t [(size_t)N_EXP * F_DIM * H_DIM];   // gate_proj^T [E][F][H]
__device__ __half g_w2t [(size_t)N_EXP * F_DIM * H_DIM];   // up_proj^T   [E][F][H]
__device__ __half g_wdt [(size_t)N_EXP * H_DIM * F_DIM];   // down_proj^T [E][H][F]
__device__ __half g_sgt [(size_t)SF_DIM * H_DIM];          // shared_gate^T [SF][H]
__device__ __half g_sut [(size_t)SF_DIM * H_DIM];          // shared_up^T   [SF][H]
__device__ __half g_sdt [(size_t)H_DIM * SF_DIM];          // shared_down^T [H][SF]
__device__ __half g_acth[(size_t)N_EXP * T_TOK * F_DIM];   // routed act fp16 (slot rows)
__device__ __half g_sacth[(size_t)T_TOK * SF_DIM];         // shared act fp16
__device__ float  g_dout[(size_t)N_EXP * T_TOK * H_DIM];   // routed down out (slot rows)

// ---------------------------------------------------------------------------
__device__ __forceinline__ uint32_t smem_u32(const void* p) {
    uint32_t a;
    asm("{ .reg .u64 t; cvta.to.shared.u64 t, %1; cvt.u32.u64 %0, t; }" : "=r"(a) : "l"(p));
    return a;
}
__device__ __forceinline__ void cpa16s(uint32_t sa, const void* g) {
    asm volatile("cp.async.cg.shared.global [%0], [%1], 16;" :: "r"(sa), "l"(g));
}
#define CP_COMMIT asm volatile("cp.async.commit_group;" ::: "memory")
#define CP_WAIT(n) asm volatile("cp.async.wait_group %0;" :: "n"(n) : "memory")

__device__ __forceinline__ void mma16(float* c, const uint32_t* a, uint32_t b0, uint32_t b1) {
    asm volatile(
        "mma.sync.aligned.m16n8k16.row.col.f32.f16.f16.f32 "
        "{%0,%1,%2,%3}, {%4,%5,%6,%7}, {%8,%9}, {%0,%1,%2,%3};"
        : "+f"(c[0]), "+f"(c[1]), "+f"(c[2]), "+f"(c[3])
        : "r"(a[0]), "r"(a[1]), "r"(a[2]), "r"(a[3]), "r"(b0), "r"(b1));
}
__device__ __forceinline__ void ldsm4(uint32_t* r, uint32_t addr) {
    asm volatile("ldmatrix.sync.aligned.m8n8.x4.shared.b16 {%0,%1,%2,%3}, [%4];"
        : "=r"(r[0]), "=r"(r[1]), "=r"(r[2]), "=r"(r[3]) : "r"(addr));
}

// ---------------------------------------------------------------------------
__global__ void zero_counts_kernel() {
    if (threadIdx.x < N_EXP) g_count[threadIdx.x] = 0;
}

// fp32 [z][R][C] -> fp16 [z][C][R]   (half2-vectorized writes, in-bounds)
__global__ void transpose_f2h_kernel(const float* __restrict__ in,
                                     __half* __restrict__ outp, int R, int C) {
    __shared__ float t[32][33];
    int tx = threadIdx.x, ty = threadIdx.y;   // (32, 8)
    int c0 = blockIdx.x * 32, r0 = blockIdx.y * 32;
    size_t zo = (size_t)blockIdx.z * R * C;
    #pragma unroll
    for (int i = 0; i < 4; i++)
        t[ty + i * 8][tx] = in[zo + (size_t)(r0 + ty + i * 8) * C + c0 + tx];
    __syncthreads();
    int r = (tx & 15) * 2;
    #pragma unroll
    for (int i = 0; i < 2; i++) {
        int c = ty + ((tx >> 4) << 3) + i * 16;
        __half2 v = __floats2half2_rn(t[r][c], t[r + 1][c]);
        *(__half2*)(outp + zo + (size_t)(c0 + c) * R + r0 + r) = v;
    }
}

// ---------------------------------------------------------------------------
// gate + top-2 routing; also emits the fp16 copy of x (fused f2h)
__global__ void gate_topk_kernel(const float* __restrict__ x,
                                 const float* __restrict__ gw) {
    __shared__ float xs[H_DIM];
    __shared__ float logits[N_EXP];
    int t = blockIdx.x;
    const float4* xr = (const float4*)(x + (size_t)t * H_DIM);
    for (int i = threadIdx.x; i < H_DIM / 4; i += blockDim.x)
        ((float4*)xs)[i] = xr[i];
    __syncthreads();

    // fp16 copy of this token row
    for (int i = threadIdx.x; i < H_DIM / 2; i += blockDim.x) {
        __half2 v = __floats2half2_rn(xs[2 * i], xs[2 * i + 1]);
        *(__half2*)(g_xh + (size_t)t * H_DIM + 2 * i) = v;
    }

    int w = threadIdx.x >> 5, lane = threadIdx.x & 31;
    if (w < N_EXP) {
        const float* gr = gw + (size_t)w * H_DIM;
        float s = 0.f;
        for (int i = lane; i < H_DIM; i += 32) s += xs[i] * gr[i];
        #pragma unroll
        for (int o = 16; o; o >>= 1) s += __shfl_xor_sync(0xffffffffu, s, o);
        if (lane == 0) logits[w] = s;
    }
    __syncthreads();

    if (threadIdx.x == 0) {
        float m = logits[0];
        #pragma unroll
        for (int e = 1; e < N_EXP; e++) m = fmaxf(m, logits[e]);
        float p[N_EXP]; float sum = 0.f;
        #pragma unroll
        for (int e = 0; e < N_EXP; e++) { p[e] = expf(logits[e] - m); sum += p[e]; }
        float inv = 1.f / sum;
        int i0 = 0;
        #pragma unroll
        for (int e = 1; e < N_EXP; e++) if (p[e] > p[i0]) i0 = e;
        int i1 = (i0 == 0) ? 1 : 0;
        #pragma unroll
        for (int e = 0; e < N_EXP; e++) if (e != i0 && p[e] > p[i1]) i1 = e;

        int s0 = atomicAdd(&g_count[i0], 1);
        g_perm[i0 * T_TOK + s0] = t;
        g_slot[2 * t]     = i0 * T_TOK + s0;
        g_tokw[2 * t]     = p[i0] * inv;
        int s1 = atomicAdd(&g_count[i1], 1);
        g_perm[i1 * T_TOK + s1] = t;
        g_slot[2 * t + 1] = i1 * T_TOK + s1;
        g_tokw[2 * t + 1] = p[i1] * inv;
    }
}

// ---------------------------------------------------------------------------
// out[t] += w0 * dout[slot0] + w1 * dout[slot1]
__global__ void combine_kernel(float* __restrict__ out) {
    int t = blockIdx.x;
    int s0 = g_slot[2 * t], s1 = g_slot[2 * t + 1];
    float w0 = g_tokw[2 * t], w1 = g_tokw[2 * t + 1];
    const float4* d0 = (const float4*)(g_dout + (size_t)s0 * H_DIM);
    const float4* d1 = (const float4*)(g_dout + (size_t)s1 * H_DIM);
    float4* o = (float4*)(out + (size_t)t * H_DIM);
    for (int i = threadIdx.x; i < H_DIM / 4; i += blockDim.x) {
        float4 a = o[i], b = d0[i], c = d1[i];
        a.x += w0 * b.x + w1 * c.x;
        a.y += w0 * b.y + w1 * c.y;
        a.z += w0 * b.z + w1 * c.z;
        a.w += w0 * b.w + w1 * c.w;
        o[i] = a;
    }
}

// ---------------------------------------------------------------------------
// act: out_fp16 = silu(A@W1t^T) * (A@W2t^T). 512 threads, block 128x128,
// warp tile 32x32 (warps 4m x 4n), ldmatrix fragment loads.
template <bool ROUTED>
__global__ void __launch_bounds__(512)
act_kernel(const __half* __restrict__ Ax,
           const __half* __restrict__ B1base,
           const __half* __restrict__ B2base,
           __half* __restrict__ outBase,
           int nld) {    // nld = N total (out pitch); KD = H_DIM
    extern __shared__ __half smem[];
    __shared__ int stok[128];
    const int KD = H_DIM;

    int e = ROUTED ? blockIdx.z : 0;
    int cnt = ROUTED ? g_count[e] : T_TOK;
    int m0 = blockIdx.y * 128;
    if (m0 >= cnt) return;
    int n0 = blockIdx.x * 128;
    int tid = threadIdx.x, wid = tid >> 5, lane = tid & 31;
    int g = lane >> 2, tg = lane & 3;
    int wm = wid & 3, wn = wid >> 2;     // 4 x 4 warps, 32x32 tiles

    if (tid < 128) {
        int slot = m0 + tid;
        stok[tid] = ROUTED ? ((slot < cnt) ? g_perm[e * T_TOK + slot]
                                           : g_perm[e * T_TOK]) : slot;
    }
    __syncthreads();

    const __half* B1 = B1base + (ROUTED ? (size_t)e * F_DIM * H_DIM : 0);
    const __half* B2 = B2base + (ROUTED ? (size_t)e * F_DIM * H_DIM : 0);
    __half* outE = outBase + (ROUTED ? (size_t)e * T_TOK * nld : 0);
    uint32_t sbase = smem_u32(smem);

    uint32_t aOff = (uint32_t)((wm * 32 + (lane & 15)) * 80 + (lane >> 4) * 16);
    uint32_t bOff = (uint32_t)((wn * 32 + (lane & 7) + (lane >> 4) * 8) * 80
                               + ((lane >> 3) & 1) * 16);

    // per stage: A rows [0,128), B1 rows [128,256), B2 rows [256,384); 80B pitch
    #define ACT_LOAD(st, k0) {                                                  \
        uint32_t base = sbase + (st) * (ACT_STAGE_H * 2);                       \
        { int r = tid >> 2, j = tid & 3;                                        \
          cpa16s(base + r * 80 + j * 16,                                        \
                 Ax + (size_t)stok[r] * KD + (k0) + j * 8);                     \
          size_t go = (size_t)(n0 + r) * KD + (k0) + j * 8;                     \
          cpa16s(base + (128 + r) * 80 + j * 16, B1 + go);                      \
          cpa16s(base + (256 + r) * 80 + j * 16, B2 + go); }                    \
        CP_COMMIT;                                                              \
    }

    float acc1[2][4][4], acc2[2][4][4];
    #pragma unroll
    for (int mt = 0; mt < 2; mt++)
        #pragma unroll
        for (int nt = 0; nt < 4; nt++)
            #pragma unroll
            for (int q = 0; q < 4; q++) { acc1[mt][nt][q] = 0.f; acc2[mt][nt][q] = 0.f; }

    const int NIT = KD / BK;   // 64
    ACT_LOAD(0, 0);
    ACT_LOAD(1, BK);

    for (int it = 0; it < NIT; ++it) {
        if (it + 1 < NIT) CP_WAIT(1); else CP_WAIT(0);
        __syncthreads();
        if (it + 2 < NIT) ACT_LOAD((it + 2) % STAGES, (it + 2) * BK);

        uint32_t stg = sbase + (it % STAGES) * (ACT_STAGE_H * 2);
        uint32_t aB = stg + aOff;
        uint32_t b1B = stg + 128 * 80 + bOff;
        uint32_t b2B = stg + 256 * 80 + bOff;

        #pragma unroll
        for (int s = 0; s < 2; s++) {   // two k16 steps
            uint32_t a[2][4];
            #pragma unroll
            for (int mt = 0; mt < 2; mt++)
                ldsm4(a[mt], aB + mt * (16 * 80) + s * 32);
            #pragma unroll
            for (int p = 0; p < 2; p++) {   // nt pairs {0,1},{2,3}
                uint32_t rb1[4], rb2[4];
                ldsm4(rb1, b1B + p * (16 * 80) + s * 32);
                ldsm4(rb2, b2B + p * (16 * 80) + s * 32);
                #pragma unroll
                for (int mt = 0; mt < 2; mt++) {
                    mma16(acc1[mt][2 * p],     a[mt], rb1[0], rb1[1]);
                    mma16(acc1[mt][2 * p + 1], a[mt], rb1[2], rb1[3]);
                    mma16(acc2[mt][2 * p],     a[mt], rb2[0], rb2[1]);
                    mma16(acc2[mt][2 * p + 1], a[mt], rb2[2], rb2[3]);
                }
            }
        }
    }
    #undef ACT_LOAD

    // epilogue: silu(g)*u -> fp16
    #pragma unroll
    for (int mt = 0; mt < 2; mt++) {
        #pragma unroll
        for (int nt = 0; nt < 4; nt++) {
            float v[4];
            #pragma unroll
            for (int q = 0; q < 4; q++) {
                float gv = acc1[mt][nt][q], uv = acc2[mt][nt][q];
                v[q] = (gv / (1.f + __expf(-gv))) * uv;
            }
            __half2 lo = __floats2half2_rn(v[0], v[1]);
            __half2 hi = __floats2half2_rn(v[2], v[3]);
            int row = m0 + wm * 32 + mt * 16 + g;
            int col = n0 + wn * 32 + nt * 8 + tg * 2;
            *(uint32_t*)(outE + (size_t)row * nld + col)       = *(uint32_t*)&lo;
            *(uint32_t*)(outE + (size_t)(row + 8) * nld + col) = *(uint32_t*)&hi;
        }
    }
}

// ---------------------------------------------------------------------------
// down: C = A @ Wd (B pre-transposed [H][KD] k-contig). 512 threads, block
// 128x128, warp tile 32x32. Plain fp32 stores (slot rows for ROUTED).
template <bool ROUTED>
__global__ void __launch_bounds__(512)
down_kernel(const __half* __restrict__ Abase,
            const __half* __restrict__ Bbase,
            float* __restrict__ out,
            int KD) {
    extern __shared__ __half smem[];

    int e = ROUTED ? blockIdx.z : 0;
    int cnt = ROUTED ? g_count[e] : T_TOK;
    int m0 = blockIdx.y * 128;
    if (m0 >= cnt) return;
    int n0 = blockIdx.x * 128;
    int tid = threadIdx.x, wid = tid >> 5, lane = tid & 31;
    int g = lane >> 2, tg = lane & 3;
    int wm = wid & 3, wn = wid >> 2;

    const __half* A = Abase + (ROUTED ? (size_t)e * T_TOK * KD : 0);
    const __half* B = Bbase + (ROUTED ? (size_t)e * H_DIM * KD : 0);
    float* outE = out + (ROUTED ? (size_t)e * T_TOK * H_DIM : 0);
    uint32_t sbase = smem_u32(smem);

    uint32_t aOff = (uint32_t)((wm * 32 + (lane & 15)) * 80 + (lane >> 4) * 16);
    uint32_t bOff = (uint32_t)((wn * 32 + (lane & 7) + (lane >> 4) * 8) * 80
                               + ((lane >> 3) & 1) * 16);

    #define DOWN_LOAD(st, k0) {                                                 \
        uint32_t base = sbase + (st) * (DOWN_STAGE_H * 2);                      \
        { int r = tid >> 2, j = tid & 3;                                        \
          cpa16s(base + r * 80 + j * 16,                                        \
                 A + (size_t)(m0 + r) * KD + (k0) + j * 8);                     \
          cpa16s(base + (128 + r) * 80 + j * 16,                                \
                 B + (size_t)(n0 + r) * KD + (k0) + j * 8); }                   \
        CP_COMMIT;                                                              \
    }

    float acc[2][4][4];
    #pragma unroll
    for (int mt = 0; mt < 2; mt++)
        #pragma unroll
        for (int nt = 0; nt < 4; nt++)
            #pragma unroll
            for (int q = 0; q < 4; q++) acc[mt][nt][q] = 0.f;

    const int NIT = KD / BK;
    DOWN_LOAD(0, 0);
    DOWN_LOAD(1, BK);

    for (int it = 0; it < NIT; ++it) {
        if (it + 1 < NIT) CP_WAIT(1); else CP_WAIT(0);
        __syncthreads();
        if (it + 2 < NIT) DOWN_LOAD((it + 2) % STAGES, (it + 2) * BK);

        uint32_t stg = sbase + (it % STAGES) * (DOWN_STAGE_H * 2);
        uint32_t aB = stg + aOff;
        uint32_t bB = stg + 128 * 80 + bOff;

        #pragma unroll
        for (int s = 0; s < 2; s++) {
            uint32_t a[2][4];
            #pragma unroll
            for (int mt = 0; mt < 2; mt++)
                ldsm4(a[mt], aB + mt * (16 * 80) + s * 32);
            #pragma unroll
            for (int p = 0; p < 2; p++) {
                uint32_t rb[4];
                ldsm4(rb, bB + p * (16 * 80) + s * 32);
                #pragma unroll
                for (int mt = 0; mt < 2; mt++) {
                    mma16(acc[mt][2 * p],     a[mt], rb[0], rb[1]);
                    mma16(acc[mt][2 * p + 1], a[mt], rb[2], rb[3]);
                }
            }
        }
    }
    #undef DOWN_LOAD

    #pragma unroll
    for (int mt = 0; mt < 2; mt++) {
        #pragma unroll
        for (int half = 0; half < 2; half++) {
            int rl = wm * 32 + mt * 16 + g + half * 8;
            float* dst = outE + (size_t)(m0 + rl) * H_DIM + n0;
            #pragma unroll
            for (int nt = 0; nt < 4; nt++) {
                int col = wn * 32 + nt * 8 + tg * 2;
                *(float2*)(dst + col) =
                    make_float2(acc[mt][nt][half * 2 + 0], acc[mt][nt][half * 2 + 1]);
            }
        }
    }
}

// ---------------------------------------------------------------------------
extern "C" void kernel_launch(void* const* d_in, const int* in_sizes, int n_in,
                              void* d_out, int out_size) {
    const float* x  = (const float*)d_in[0];
    const float* gw = (const float*)d_in[1];
    const float* gp = (const float*)d_in[2];
    const float* up = (const float*)d_in[3];
    const float* dp = (const float*)d_in[4];
    const float* sg = (const float*)d_in[5];
    const float* su = (const float*)d_in[6];
    const float* sd = (const float*)d_in[7];
    float* out = (float*)d_out;

    __half *xhP, *w1tP, *w2tP, *wdtP, *sgtP, *sutP, *sdtP, *acthP, *sacthP;
    float* doutP;
    cudaGetSymbolAddress((void**)&xhP,    g_xh);
    cudaGetSymbolAddress((void**)&w1tP,   g_w1t);
    cudaGetSymbolAddress((void**)&w2tP,   g_w2t);
    cudaGetSymbolAddress((void**)&wdtP,   g_wdt);
    cudaGetSymbolAddress((void**)&sgtP,   g_sgt);
    cudaGetSymbolAddress((void**)&sutP,   g_sut);
    cudaGetSymbolAddress((void**)&sdtP,   g_sdt);
    cudaGetSymbolAddress((void**)&acthP,  g_acth);
    cudaGetSymbolAddress((void**)&sacthP, g_sacth);
    cudaGetSymbolAddress((void**)&doutP,  g_dout);

    cudaFuncSetAttribute(act_kernel<true>,   cudaFuncAttributeMaxDynamicSharedMemorySize, ACT_SMEM);
    cudaFuncSetAttribute(act_kernel<false>,  cudaFuncAttributeMaxDynamicSharedMemorySize, ACT_SMEM);
    cudaFuncSetAttribute(down_kernel<true>,  cudaFuncAttributeMaxDynamicSharedMemorySize, DOWN_SMEM);
    cudaFuncSetAttribute(down_kernel<false>, cudaFuncAttributeMaxDynamicSharedMemorySize, DOWN_SMEM);

    // one-time side stream + events (created outside any graph capture: the
    // harness's first call is the eager correctness run). No device allocations.
    static cudaStream_t s1 = nullptr;
    static cudaEvent_t evFork = nullptr, evJoin = nullptr;
    if (s1 == nullptr) {
        cudaStreamCreateWithFlags(&s1, cudaStreamNonBlocking);
        cudaEventCreateWithFlags(&evFork, cudaEventDisableTiming);
        cudaEventCreateWithFlags(&evJoin, cudaEventDisableTiming);
    }

    dim3 tb(32, 8);

    // s0: gating (also produces xh)
    zero_counts_kernel<<<1, 32>>>();
    gate_topk_kernel<<<T_TOK, 256>>>(x, gw);

    // fork: routed chain on s1 (needs gate results + xh)
    cudaEventRecord(evFork, 0);
    cudaStreamWaitEvent(s1, evFork, 0);

    // s1: routed weights convert -> routed act -> routed down
    transpose_f2h_kernel<<<dim3(F_DIM / 32, H_DIM / 32, N_EXP), tb, 0, s1>>>(gp, w1tP, H_DIM, F_DIM);
    transpose_f2h_kernel<<<dim3(F_DIM / 32, H_DIM / 32, N_EXP), tb, 0, s1>>>(up, w2tP, H_DIM, F_DIM);
    transpose_f2h_kernel<<<dim3(H_DIM / 32, F_DIM / 32, N_EXP), tb, 0, s1>>>(dp, wdtP, F_DIM, H_DIM);
    act_kernel<true><<<dim3(F_DIM / 128, T_TOK / 128, N_EXP), 512, ACT_SMEM, s1>>>(xhP, w1tP, w2tP, acthP, F_DIM);
    down_kernel<true><<<dim3(H_DIM / 128, T_TOK / 128, N_EXP), 512, DOWN_SMEM, s1>>>(acthP, wdtP, doutP, F_DIM);
    cudaEventRecord(evJoin, s1);

    // s0: shared chain (runs concurrent with s1)
    transpose_f2h_kernel<<<dim3(SF_DIM / 32, H_DIM / 32, 1), tb>>>(sg, sgtP, H_DIM, SF_DIM);
    transpose_f2h_kernel<<<dim3(SF_DIM / 32, H_DIM / 32, 1), tb>>>(su, sutP, H_DIM, SF_DIM);
    transpose_f2h_kernel<<<dim3(H_DIM / 32, SF_DIM / 32, 1), tb>>>(sd, sdtP, SF_DIM, H_DIM);
    act_kernel<false><<<dim3(SF_DIM / 128, T_TOK / 128, 1), 512, ACT_SMEM>>>(xhP, sgtP, sutP, sacthP, SF_DIM);
    down_kernel<false><<<dim3(H_DIM / 128, T_TOK / 128, 1), 512, DOWN_SMEM>>>(sacthP, sdtP, out, SF_DIM);

    // join: combine needs both chains
    cudaStreamWaitEvent(0, evJoin, 0);
    combine_kernel<<<T_TOK, 256>>>(out);
}

// round 13
// speedup vs baseline: 6.7646x; 1.0941x over previous
#include <cuda_runtime.h>
#include <cuda_fp16.h>
#include <cstdint>

#define T_TOK 2048
#define H_DIM 2048
#define F_DIM 1408
#define SF_DIM 2816
#define N_EXP 8

#define BK 64
#define STAGES 3
#define PITCH 144                                // bytes per smem row (64 halves + 16B pad)
#define ACT_STAGE_B (384 * PITCH)                // A(128) + B1(128) + B2(128) rows
#define DOWN_STAGE_B (256 * PITCH)               // A(128) + B(128)
#define ACT_SMEM (STAGES * ACT_STAGE_B)          // 165888 B
#define DOWN_SMEM (STAGES * DOWN_STAGE_B)        // 110592 B

// ---- scratch (device globals: no allocations allowed) ----
__device__ int    g_count[N_EXP];
__device__ int    g_perm[N_EXP * T_TOK];
__device__ int    g_slot[2 * T_TOK];
__device__ float  g_tokw[2 * T_TOK];
__device__ __half g_xh  [(size_t)T_TOK * H_DIM];
__device__ __half g_w1t [(size_t)N_EXP * F_DIM * H_DIM];
__device__ __half g_w2t [(size_t)N_EXP * F_DIM * H_DIM];
__device__ __half g_wdt [(size_t)N_EXP * H_DIM * F_DIM];
__device__ __half g_sgt [(size_t)SF_DIM * H_DIM];
__device__ __half g_sut [(size_t)SF_DIM * H_DIM];
__device__ __half g_sdt [(size_t)H_DIM * SF_DIM];
__device__ __half g_acth[(size_t)N_EXP * T_TOK * F_DIM];
__device__ __half g_sacth[(size_t)T_TOK * SF_DIM];
__device__ float  g_dout[(size_t)N_EXP * T_TOK * H_DIM];

// ---------------------------------------------------------------------------
__device__ __forceinline__ uint32_t smem_u32(const void* p) {
    uint32_t a;
    asm("{ .reg .u64 t; cvta.to.shared.u64 t, %1; cvt.u32.u64 %0, t; }" : "=r"(a) : "l"(p));
    return a;
}
__device__ __forceinline__ void cpa16s(uint32_t sa, const void* g) {
    asm volatile("cp.async.cg.shared.global [%0], [%1], 16;" :: "r"(sa), "l"(g));
}
#define CP_COMMIT asm volatile("cp.async.commit_group;" ::: "memory")
#define CP_WAIT(n) asm volatile("cp.async.wait_group %0;" :: "n"(n) : "memory")

__device__ __forceinline__ void mma16(float* c, const uint32_t* a, uint32_t b0, uint32_t b1) {
    asm volatile(
        "mma.sync.aligned.m16n8k16.row.col.f32.f16.f16.f32 "
        "{%0,%1,%2,%3}, {%4,%5,%6,%7}, {%8,%9}, {%0,%1,%2,%3};"
        : "+f"(c[0]), "+f"(c[1]), "+f"(c[2]), "+f"(c[3])
        : "r"(a[0]), "r"(a[1]), "r"(a[2]), "r"(a[3]), "r"(b0), "r"(b1));
}
__device__ __forceinline__ void ldsm4(uint32_t* r, uint32_t addr) {
    asm volatile("ldmatrix.sync.aligned.m8n8.x4.shared.b16 {%0,%1,%2,%3}, [%4];"
        : "=r"(r[0]), "=r"(r[1]), "=r"(r[2]), "=r"(r[3]) : "r"(addr));
}

// ---------------------------------------------------------------------------
__global__ void zero_counts_kernel() {
    if (threadIdx.x < N_EXP) g_count[threadIdx.x] = 0;
}

// fp32 [z][R][C] -> fp16 [z][C][R]; 64-row x 32-col tiles, 128B coalesced writes
__global__ void transpose_f2h_kernel(const float* __restrict__ in,
                                     __half* __restrict__ outp, int R, int C) {
    __shared__ float t[32][65];   // [col][row], 65-word pitch
    int tx = threadIdx.x, ty = threadIdx.y;   // (32, 8)
    int c0 = blockIdx.x * 32, r0 = blockIdx.y * 64;
    size_t zo = (size_t)blockIdx.z * R * C;
    #pragma unroll
    for (int i = 0; i < 8; i++) {
        int r = ty + i * 8;
        t[tx][r] = in[zo + (size_t)(r0 + r) * C + c0 + tx];
    }
    __syncthreads();
    #pragma unroll
    for (int i = 0; i < 4; i++) {
        int c = ty + i * 8;
        __half2 v = __floats2half2_rn(t[c][2 * tx], t[c][2 * tx + 1]);
        *(__half2*)(outp + zo + (size_t)(c0 + c) * R + r0 + 2 * tx) = v;
    }
}

// ---------------------------------------------------------------------------
// gate + top-2 routing; also emits the fp16 copy of x (fused f2h)
__global__ void gate_topk_kernel(const float* __restrict__ x,
                                 const float* __restrict__ gw) {
    __shared__ float xs[H_DIM];
    __shared__ float logits[N_EXP];
    int t = blockIdx.x;
    const float4* xr = (const float4*)(x + (size_t)t * H_DIM);
    for (int i = threadIdx.x; i < H_DIM / 4; i += blockDim.x)
        ((float4*)xs)[i] = xr[i];
    __syncthreads();

    for (int i = threadIdx.x; i < H_DIM / 2; i += blockDim.x) {
        __half2 v = __floats2half2_rn(xs[2 * i], xs[2 * i + 1]);
        *(__half2*)(g_xh + (size_t)t * H_DIM + 2 * i) = v;
    }

    int w = threadIdx.x >> 5, lane = threadIdx.x & 31;
    if (w < N_EXP) {
        const float* gr = gw + (size_t)w * H_DIM;
        float s = 0.f;
        for (int i = lane; i < H_DIM; i += 32) s += xs[i] * gr[i];
        #pragma unroll
        for (int o = 16; o; o >>= 1) s += __shfl_xor_sync(0xffffffffu, s, o);
        if (lane == 0) logits[w] = s;
    }
    __syncthreads();

    if (threadIdx.x == 0) {
        float m = logits[0];
        #pragma unroll
        for (int e = 1; e < N_EXP; e++) m = fmaxf(m, logits[e]);
        float p[N_EXP]; float sum = 0.f;
        #pragma unroll
        for (int e = 0; e < N_EXP; e++) { p[e] = expf(logits[e] - m); sum += p[e]; }
        float inv = 1.f / sum;
        int i0 = 0;
        #pragma unroll
        for (int e = 1; e < N_EXP; e++) if (p[e] > p[i0]) i0 = e;
        int i1 = (i0 == 0) ? 1 : 0;
        #pragma unroll
        for (int e = 0; e < N_EXP; e++) if (e != i0 && p[e] > p[i1]) i1 = e;

        int s0 = atomicAdd(&g_count[i0], 1);
        g_perm[i0 * T_TOK + s0] = t;
        g_slot[2 * t]     = i0 * T_TOK + s0;
        g_tokw[2 * t]     = p[i0] * inv;
        int s1 = atomicAdd(&g_count[i1], 1);
        g_perm[i1 * T_TOK + s1] = t;
        g_slot[2 * t + 1] = i1 * T_TOK + s1;
        g_tokw[2 * t + 1] = p[i1] * inv;
    }
}

// ---------------------------------------------------------------------------
__global__ void combine_kernel(float* __restrict__ out) {
    int t = blockIdx.x;
    int s0 = g_slot[2 * t], s1 = g_slot[2 * t + 1];
    float w0 = g_tokw[2 * t], w1 = g_tokw[2 * t + 1];
    const float4* d0 = (const float4*)(g_dout + (size_t)s0 * H_DIM);
    const float4* d1 = (const float4*)(g_dout + (size_t)s1 * H_DIM);
    float4* o = (float4*)(out + (size_t)t * H_DIM);
    for (int i = threadIdx.x; i < H_DIM / 4; i += blockDim.x) {
        float4 a = o[i], b = d0[i], c = d1[i];
        a.x += w0 * b.x + w1 * c.x;
        a.y += w0 * b.y + w1 * c.y;
        a.z += w0 * b.z + w1 * c.z;
        a.w += w0 * b.w + w1 * c.w;
        o[i] = a;
    }
}

// ---------------------------------------------------------------------------
// act: out_fp16 = silu(A@W1t^T) * (A@W2t^T). 512 threads, block 128x128,
// warp tile 32x32 (4m x 4n warps), BK=64 slabs, ldmatrix fragment loads.
template <bool ROUTED>
__global__ void __launch_bounds__(512)
act_kernel(const __half* __restrict__ Ax,
           const __half* __restrict__ B1base,
           const __half* __restrict__ B2base,
           __half* __restrict__ outBase,
           int nld) {    // nld = N total (out pitch); KD = H_DIM
    extern __shared__ __half smem[];
    __shared__ int stok[128];
    const int KD = H_DIM;

    int e = ROUTED ? blockIdx.z : 0;
    int cnt = ROUTED ? g_count[e] : T_TOK;
    int m0 = blockIdx.y * 128;
    if (m0 >= cnt) return;
    int n0 = blockIdx.x * 128;
    int tid = threadIdx.x, wid = tid >> 5, lane = tid & 31;
    int g = lane >> 2, tg = lane & 3;
    int wm = wid & 3, wn = wid >> 2;

    if (tid < 128) {
        int slot = m0 + tid;
        stok[tid] = ROUTED ? ((slot < cnt) ? g_perm[e * T_TOK + slot]
                                           : g_perm[e * T_TOK]) : slot;
    }
    __syncthreads();

    const __half* B1 = B1base + (ROUTED ? (size_t)e * F_DIM * H_DIM : 0);
    const __half* B2 = B2base + (ROUTED ? (size_t)e * F_DIM * H_DIM : 0);
    __half* outE = outBase + (ROUTED ? (size_t)e * T_TOK * nld : 0);
    uint32_t sbase = smem_u32(smem);

    uint32_t aOff = (uint32_t)((wm * 32 + (lane & 15)) * PITCH + (lane >> 4) * 16);
    uint32_t bOff = (uint32_t)((wn * 32 + (lane & 7) + (lane >> 4) * 8) * PITCH
                               + ((lane >> 3) & 1) * 16);

    // per stage: A rows [0,128), B1 [128,256), B2 [256,384); PITCH bytes/row
    #define ACT_LOAD(st, k0) {                                                  \
        uint32_t base = sbase + (st) * ACT_STAGE_B;                             \
        _Pragma("unroll")                                                       \
        for (int i = 0; i < 2; i++) {                                           \
            int id = tid + i * 512; int r = id >> 3, j = id & 7;                \
            cpa16s(base + r * PITCH + j * 16,                                   \
                   Ax + (size_t)stok[r] * KD + (k0) + j * 8);                   \
            size_t go = (size_t)(n0 + r) * KD + (k0) + j * 8;                   \
            cpa16s(base + (128 + r) * PITCH + j * 16, B1 + go);                 \
            cpa16s(base + (256 + r) * PITCH + j * 16, B2 + go);                 \
        }                                                                       \
        CP_COMMIT;                                                              \
    }

    float acc1[2][4][4], acc2[2][4][4];
    #pragma unroll
    for (int mt = 0; mt < 2; mt++)
        #pragma unroll
        for (int nt = 0; nt < 4; nt++)
            #pragma unroll
            for (int q = 0; q < 4; q++) { acc1[mt][nt][q] = 0.f; acc2[mt][nt][q] = 0.f; }

    const int NIT = KD / BK;   // 32
    ACT_LOAD(0, 0);
    ACT_LOAD(1, BK);

    for (int it = 0; it < NIT; ++it) {
        if (it + 1 < NIT) CP_WAIT(1); else CP_WAIT(0);
        __syncthreads();
        if (it + 2 < NIT) ACT_LOAD((it + 2) % STAGES, (it + 2) * BK);

        uint32_t stg = sbase + (it % STAGES) * ACT_STAGE_B;
        uint32_t aB = stg + aOff;
        uint32_t b1B = stg + 128 * PITCH + bOff;
        uint32_t b2B = stg + 256 * PITCH + bOff;

        #pragma unroll
        for (int s = 0; s < 4; s++) {   // four k16 steps
            uint32_t a[2][4];
            #pragma unroll
            for (int mt = 0; mt < 2; mt++)
                ldsm4(a[mt], aB + mt * (16 * PITCH) + s * 32);
            #pragma unroll
            for (int p = 0; p < 2; p++) {
                uint32_t rb1[4], rb2[4];
                ldsm4(rb1, b1B + p * (16 * PITCH) + s * 32);
                ldsm4(rb2, b2B + p * (16 * PITCH) + s * 32);
                #pragma unroll
                for (int mt = 0; mt < 2; mt++) {
                    mma16(acc1[mt][2 * p],     a[mt], rb1[0], rb1[1]);
                    mma16(acc1[mt][2 * p + 1], a[mt], rb1[2], rb1[3]);
                    mma16(acc2[mt][2 * p],     a[mt], rb2[0], rb2[1]);
                    mma16(acc2[mt][2 * p + 1], a[mt], rb2[2], rb2[3]);
                }
            }
        }
    }
    #undef ACT_LOAD

    #pragma unroll
    for (int mt = 0; mt < 2; mt++) {
        #pragma unroll
        for (int nt = 0; nt < 4; nt++) {
            float v[4];
            #pragma unroll
            for (int q = 0; q < 4; q++) {
                float gv = acc1[mt][nt][q], uv = acc2[mt][nt][q];
                v[q] = (gv / (1.f + __expf(-gv))) * uv;
            }
            __half2 lo = __floats2half2_rn(v[0], v[1]);
            __half2 hi = __floats2half2_rn(v[2], v[3]);
            int row = m0 + wm * 32 + mt * 16 + g;
            int col = n0 + wn * 32 + nt * 8 + tg * 2;
            *(uint32_t*)(outE + (size_t)row * nld + col)       = *(uint32_t*)&lo;
            *(uint32_t*)(outE + (size_t)(row + 8) * nld + col) = *(uint32_t*)&hi;
        }
    }
}

// ---------------------------------------------------------------------------
// down: C = A @ Wd (B pre-transposed [H][KD] k-contig). 512 threads, BK=64.
template <bool ROUTED>
__global__ void __launch_bounds__(512)
down_kernel(const __half* __restrict__ Abase,
            const __half* __restrict__ Bbase,
            float* __restrict__ out,
            int KD) {
    extern __shared__ __half smem[];

    int e = ROUTED ? blockIdx.z : 0;
    int cnt = ROUTED ? g_count[e] : T_TOK;
    int m0 = blockIdx.y * 128;
    if (m0 >= cnt) return;
    int n0 = blockIdx.x * 128;
    int tid = threadIdx.x, wid = tid >> 5, lane = tid & 31;
    int g = lane >> 2, tg = lane & 3;
    int wm = wid & 3, wn = wid >> 2;

    const __half* A = Abase + (ROUTED ? (size_t)e * T_TOK * KD : 0);
    const __half* B = Bbase + (ROUTED ? (size_t)e * H_DIM * KD : 0);
    float* outE = out + (ROUTED ? (size_t)e * T_TOK * H_DIM : 0);
    uint32_t sbase = smem_u32(smem);

    uint32_t aOff = (uint32_t)((wm * 32 + (lane & 15)) * PITCH + (lane >> 4) * 16);
    uint32_t bOff = (uint32_t)((wn * 32 + (lane & 7) + (lane >> 4) * 8) * PITCH
                               + ((lane >> 3) & 1) * 16);

    #define DOWN_LOAD(st, k0) {                                                 \
        uint32_t base = sbase + (st) * DOWN_STAGE_B;                            \
        _Pragma("unroll")                                                       \
        for (int i = 0; i < 2; i++) {                                           \
            int id = tid + i * 512; int r = id >> 3, j = id & 7;                \
            cpa16s(base + r * PITCH + j * 16,                                   \
                   A + (size_t)(m0 + r) * KD + (k0) + j * 8);                   \
            cpa16s(base + (128 + r) * PITCH + j * 16,                           \
                   B + (size_t)(n0 + r) * KD + (k0) + j * 8);                   \
        }                                                                       \
        CP_COMMIT;                                                              \
    }

    float acc[2][4][4];
    #pragma unroll
    for (int mt = 0; mt < 2; mt++)
        #pragma unroll
        for (int nt = 0; nt < 4; nt++)
            #pragma unroll
            for (int q = 0; q < 4; q++) acc[mt][nt][q] = 0.f;

    const int NIT = KD / BK;   // 22 or 44
    DOWN_LOAD(0, 0);
    DOWN_LOAD(1, BK);

    for (int it = 0; it < NIT; ++it) {
        if (it + 1 < NIT) CP_WAIT(1); else CP_WAIT(0);
        __syncthreads();
        if (it + 2 < NIT) DOWN_LOAD((it + 2) % STAGES, (it + 2) * BK);

        uint32_t stg = sbase + (it % STAGES) * DOWN_STAGE_B;
        uint32_t aB = stg + aOff;
        uint32_t bB = stg + 128 * PITCH + bOff;

        #pragma unroll
        for (int s = 0; s < 4; s++) {
            uint32_t a[2][4];
            #pragma unroll
            for (int mt = 0; mt < 2; mt++)
                ldsm4(a[mt], aB + mt * (16 * PITCH) + s * 32);
            #pragma unroll
            for (int p = 0; p < 2; p++) {
                uint32_t rb[4];
                ldsm4(rb, bB + p * (16 * PITCH) + s * 32);
                #pragma unroll
                for (int mt = 0; mt < 2; mt++) {
                    mma16(acc[mt][2 * p],     a[mt], rb[0], rb[1]);
                    mma16(acc[mt][2 * p + 1], a[mt], rb[2], rb[3]);
                }
            }
        }
    }
    #undef DOWN_LOAD

    #pragma unroll
    for (int mt = 0; mt < 2; mt++) {
        #pragma unroll
        for (int half = 0; half < 2; half++) {
            int rl = wm * 32 + mt * 16 + g + half * 8;
            float* dst = outE + (size_t)(m0 + rl) * H_DIM + n0;
            #pragma unroll
            for (int nt = 0; nt < 4; nt++) {
                int col = wn * 32 + nt * 8 + tg * 2;
                *(float2*)(dst + col) =
                    make_float2(acc[mt][nt][half * 2 + 0], acc[mt][nt][half * 2 + 1]);
            }
        }
    }
}

// ---------------------------------------------------------------------------
extern "C" void kernel_launch(void* const* d_in, const int* in_sizes, int n_in,
                              void* d_out, int out_size) {
    const float* x  = (const float*)d_in[0];
    const float* gw = (const float*)d_in[1];
    const float* gp = (const float*)d_in[2];
    const float* up = (const float*)d_in[3];
    const float* dp = (const float*)d_in[4];
    const float* sg = (const float*)d_in[5];
    const float* su = (const float*)d_in[6];
    const float* sd = (const float*)d_in[7];
    float* out = (float*)d_out;

    __half *xhP, *w1tP, *w2tP, *wdtP, *sgtP, *sutP, *sdtP, *acthP, *sacthP;
    float* doutP;
    cudaGetSymbolAddress((void**)&xhP,    g_xh);
    cudaGetSymbolAddress((void**)&w1tP,   g_w1t);
    cudaGetSymbolAddress((void**)&w2tP,   g_w2t);
    cudaGetSymbolAddress((void**)&wdtP,   g_wdt);
    cudaGetSymbolAddress((void**)&sgtP,   g_sgt);
    cudaGetSymbolAddress((void**)&sutP,   g_sut);
    cudaGetSymbolAddress((void**)&sdtP,   g_sdt);
    cudaGetSymbolAddress((void**)&acthP,  g_acth);
    cudaGetSymbolAddress((void**)&sacthP, g_sacth);
    cudaGetSymbolAddress((void**)&doutP,  g_dout);

    cudaFuncSetAttribute(act_kernel<true>,   cudaFuncAttributeMaxDynamicSharedMemorySize, ACT_SMEM);
    cudaFuncSetAttribute(act_kernel<false>,  cudaFuncAttributeMaxDynamicSharedMemorySize, ACT_SMEM);
    cudaFuncSetAttribute(down_kernel<true>,  cudaFuncAttributeMaxDynamicSharedMemorySize, DOWN_SMEM);
    cudaFuncSetAttribute(down_kernel<false>, cudaFuncAttributeMaxDynamicSharedMemorySize, DOWN_SMEM);

    // one-time side stream + events (created outside graph capture)
    static cudaStream_t s1 = nullptr;
    static cudaEvent_t evFork = nullptr, evJoin = nullptr, evDp = nullptr;
    if (s1 == nullptr) {
        cudaStreamCreateWithFlags(&s1, cudaStreamNonBlocking);
        cudaEventCreateWithFlags(&evFork, cudaEventDisableTiming);
        cudaEventCreateWithFlags(&evJoin, cudaEventDisableTiming);
        cudaEventCreateWithFlags(&evDp,   cudaEventDisableTiming);
    }

    dim3 tb(32, 8);

    // s0: gating (also produces xh)
    zero_counts_kernel<<<1, 32>>>();
    gate_topk_kernel<<<T_TOK, 256>>>(x, gw);

    // fork: routed chain on s1 (needs gate results + xh)
    cudaEventRecord(evFork, 0);
    cudaStreamWaitEvent(s1, evFork, 0);

    // s1: gate/up weight transposes -> routed act
    transpose_f2h_kernel<<<dim3(F_DIM / 32, H_DIM / 64, N_EXP), tb, 0, s1>>>(gp, w1tP, H_DIM, F_DIM);
    transpose_f2h_kernel<<<dim3(F_DIM / 32, H_DIM / 64, N_EXP), tb, 0, s1>>>(up, w2tP, H_DIM, F_DIM);
    act_kernel<true><<<dim3(F_DIM / 128, T_TOK / 128, N_EXP), 512, ACT_SMEM, s1>>>(xhP, w1tP, w2tP, acthP, F_DIM);

    // s0: dp transpose, recorded BEFORE s1 waits on it (capture-order requirement)
    transpose_f2h_kernel<<<dim3(H_DIM / 32, F_DIM / 64, N_EXP), tb>>>(dp, wdtP, F_DIM, H_DIM);
    cudaEventRecord(evDp, 0);

    // s1: routed down (needs dp transpose) -> join event
    cudaStreamWaitEvent(s1, evDp, 0);
    down_kernel<true><<<dim3(H_DIM / 128, T_TOK / 128, N_EXP), 512, DOWN_SMEM, s1>>>(acthP, wdtP, doutP, F_DIM);
    cudaEventRecord(evJoin, s1);

    // s0: shared chain (concurrent with s1)
    transpose_f2h_kernel<<<dim3(SF_DIM / 32, H_DIM / 64, 1), tb>>>(sg, sgtP, H_DIM, SF_DIM);
    transpose_f2h_kernel<<<dim3(SF_DIM / 32, H_DIM / 64, 1), tb>>>(su, sutP, H_DIM, SF_DIM);
    transpose_f2h_kernel<<<dim3(H_DIM / 32, SF_DIM / 64, 1), tb>>>(sd, sdtP, SF_DIM, H_DIM);
    act_kernel<false><<<dim3(SF_DIM / 128, T_TOK / 128, 1), 512, ACT_SMEM>>>(xhP, sgtP, sutP, sacthP, SF_DIM);
    down_kernel<false><<<dim3(H_DIM / 128, T_TOK / 128, 1), 512, DOWN_SMEM>>>(sacthP, sdtP, out, SF_DIM);

    // join: combine needs both chains
    cudaStreamWaitEvent(0, evJoin, 0);
    combine_kernel<<<T_TOK, 256>>>(out);
}

// round 15
// speedup vs baseline: 6.8184x; 1.0080x over previous
#include <cuda_runtime.h>
#include <cuda_fp16.h>
#include <cstdint>

#define T_TOK 2048
#define H_DIM 2048
#define F_DIM 1408
#define SF_DIM 2816
#define N_EXP 8

#define BK 64
#define STAGES 3
#define PITCH 144                                // bytes per smem row (64 halves + 16B pad)
#define ACT_STAGE_B (384 * PITCH)                // A(128) + B1(128) + B2(128) rows
#define DOWN_STAGE_B (256 * PITCH)               // A(128) + B(128)
#define ACT_SMEM (STAGES * ACT_STAGE_B)          // 165888 B
#define DOWN_SMEM (STAGES * DOWN_STAGE_B)        // 110592 B

// ---- scratch (device globals: no allocations allowed) ----
__device__ int    g_count[N_EXP];
__device__ int    g_perm[N_EXP * T_TOK];
__device__ int    g_slot[2 * T_TOK];
__device__ float  g_tokw[2 * T_TOK];
__device__ __half g_xh  [(size_t)T_TOK * H_DIM];
__device__ __half g_w1t [(size_t)N_EXP * F_DIM * H_DIM];
__device__ __half g_w2t [(size_t)N_EXP * F_DIM * H_DIM];
__device__ __half g_wdt [(size_t)N_EXP * H_DIM * F_DIM];
__device__ __half g_sgt [(size_t)SF_DIM * H_DIM];
__device__ __half g_sut [(size_t)SF_DIM * H_DIM];
__device__ __half g_sdt [(size_t)H_DIM * SF_DIM];
__device__ __half g_acth[(size_t)N_EXP * T_TOK * F_DIM];
__device__ __half g_sacth[(size_t)T_TOK * SF_DIM];
__device__ float  g_dout[(size_t)N_EXP * T_TOK * H_DIM];

// ---------------------------------------------------------------------------
__device__ __forceinline__ uint32_t smem_u32(const void* p) {
    uint32_t a;
    asm("{ .reg .u64 t; cvta.to.shared.u64 t, %1; cvt.u32.u64 %0, t; }" : "=r"(a) : "l"(p));
    return a;
}
__device__ __forceinline__ void cpa16s(uint32_t sa, const void* g) {
    asm volatile("cp.async.cg.shared.global [%0], [%1], 16;" :: "r"(sa), "l"(g));
}
#define CP_COMMIT asm volatile("cp.async.commit_group;" ::: "memory")
#define CP_WAIT(n) asm volatile("cp.async.wait_group %0;" :: "n"(n) : "memory")

__device__ __forceinline__ void mma16(float* c, const uint32_t* a, uint32_t b0, uint32_t b1) {
    asm volatile(
        "mma.sync.aligned.m16n8k16.row.col.f32.f16.f16.f32 "
        "{%0,%1,%2,%3}, {%4,%5,%6,%7}, {%8,%9}, {%0,%1,%2,%3};"
        : "+f"(c[0]), "+f"(c[1]), "+f"(c[2]), "+f"(c[3])
        : "r"(a[0]), "r"(a[1]), "r"(a[2]), "r"(a[3]), "r"(b0), "r"(b1));
}
__device__ __forceinline__ void ldsm4(uint32_t* r, uint32_t addr) {
    asm volatile("ldmatrix.sync.aligned.m8n8.x4.shared.b16 {%0,%1,%2,%3}, [%4];"
        : "=r"(r[0]), "=r"(r[1]), "=r"(r[2]), "=r"(r[3]) : "r"(addr));
}

// ---------------------------------------------------------------------------
__global__ void zero_counts_kernel() {
    if (threadIdx.x < N_EXP) g_count[threadIdx.x] = 0;
}

// fp32 [z][R][C] -> fp16 [z][C][R]; 64-row x 32-col tiles, 128B coalesced writes
__global__ void transpose_f2h_kernel(const float* __restrict__ in,
                                     __half* __restrict__ outp, int R, int C) {
    __shared__ float t[32][65];   // [col][row], 65-word pitch
    int tx = threadIdx.x, ty = threadIdx.y;   // (32, 8)
    int c0 = blockIdx.x * 32, r0 = blockIdx.y * 64;
    size_t zo = (size_t)blockIdx.z * R * C;
    #pragma unroll
    for (int i = 0; i < 8; i++) {
        int r = ty + i * 8;
        t[tx][r] = in[zo + (size_t)(r0 + r) * C + c0 + tx];
    }
    __syncthreads();
    #pragma unroll
    for (int i = 0; i < 4; i++) {
        int c = ty + i * 8;
        __half2 v = __floats2half2_rn(t[c][2 * tx], t[c][2 * tx + 1]);
        *(__half2*)(outp + zo + (size_t)(c0 + c) * R + r0 + 2 * tx) = v;
    }
}

// ---------------------------------------------------------------------------
// gate + top-2 routing; also emits the fp16 copy of x (fused f2h)
__global__ void gate_topk_kernel(const float* __restrict__ x,
                                 const float* __restrict__ gw) {
    __shared__ float xs[H_DIM];
    __shared__ float logits[N_EXP];
    int t = blockIdx.x;
    const float4* xr = (const float4*)(x + (size_t)t * H_DIM);
    for (int i = threadIdx.x; i < H_DIM / 4; i += blockDim.x)
        ((float4*)xs)[i] = xr[i];
    __syncthreads();

    for (int i = threadIdx.x; i < H_DIM / 2; i += blockDim.x) {
        __half2 v = __floats2half2_rn(xs[2 * i], xs[2 * i + 1]);
        *(__half2*)(g_xh + (size_t)t * H_DIM + 2 * i) = v;
    }

    int w = threadIdx.x >> 5, lane = threadIdx.x & 31;
    if (w < N_EXP) {
        const float* gr = gw + (size_t)w * H_DIM;
        float s = 0.f;
        for (int i = lane; i < H_DIM; i += 32) s += xs[i] * gr[i];
        #pragma unroll
        for (int o = 16; o; o >>= 1) s += __shfl_xor_sync(0xffffffffu, s, o);
        if (lane == 0) logits[w] = s;
    }
    __syncthreads();

    if (threadIdx.x == 0) {
        float m = logits[0];
        #pragma unroll
        for (int e = 1; e < N_EXP; e++) m = fmaxf(m, logits[e]);
        float p[N_EXP]; float sum = 0.f;
        #pragma unroll
        for (int e = 0; e < N_EXP; e++) { p[e] = expf(logits[e] - m); sum += p[e]; }
        float inv = 1.f / sum;
        int i0 = 0;
        #pragma unroll
        for (int e = 1; e < N_EXP; e++) if (p[e] > p[i0]) i0 = e;
        int i1 = (i0 == 0) ? 1 : 0;
        #pragma unroll
        for (int e = 0; e < N_EXP; e++) if (e != i0 && p[e] > p[i1]) i1 = e;

        int s0 = atomicAdd(&g_count[i0], 1);
        g_perm[i0 * T_TOK + s0] = t;
        g_slot[2 * t]     = i0 * T_TOK + s0;
        g_tokw[2 * t]     = p[i0] * inv;
        int s1 = atomicAdd(&g_count[i1], 1);
        g_perm[i1 * T_TOK + s1] = t;
        g_slot[2 * t + 1] = i1 * T_TOK + s1;
        g_tokw[2 * t + 1] = p[i1] * inv;
    }
}

// ---------------------------------------------------------------------------
__global__ void combine_kernel(float* __restrict__ out) {
    int t = blockIdx.x;
    int s0 = g_slot[2 * t], s1 = g_slot[2 * t + 1];
    float w0 = g_tokw[2 * t], w1 = g_tokw[2 * t + 1];
    const float4* d0 = (const float4*)(g_dout + (size_t)s0 * H_DIM);
    const float4* d1 = (const float4*)(g_dout + (size_t)s1 * H_DIM);
    float4* o = (float4*)(out + (size_t)t * H_DIM);
    for (int i = threadIdx.x; i < H_DIM / 4; i += blockDim.x) {
        float4 a = o[i], b = d0[i], c = d1[i];
        a.x += w0 * b.x + w1 * c.x;
        a.y += w0 * b.y + w1 * c.y;
        a.z += w0 * b.z + w1 * c.z;
        a.w += w0 * b.w + w1 * c.w;
        o[i] = a;
    }
}

// ---------------------------------------------------------------------------
// act: out_fp16 = silu(A@W1t^T) * (A@W2t^T). 512 threads, block 128x128,
// warp tile 32x32 (4m x 4n warps), BK=64 slabs, ldmatrix fragment loads.
template <bool ROUTED>
__global__ void __launch_bounds__(512)
act_kernel(const __half* __restrict__ Ax,
           const __half* __restrict__ B1base,
           const __half* __restrict__ B2base,
           __half* __restrict__ outBase,
           int nld) {    // nld = N total (out pitch); KD = H_DIM
    extern __shared__ __half smem[];
    __shared__ int stok[128];
    const int KD = H_DIM;

    int e = ROUTED ? blockIdx.z : 0;
    int cnt = ROUTED ? g_count[e] : T_TOK;
    int m0 = blockIdx.y * 128;
    if (m0 >= cnt) return;
    int n0 = blockIdx.x * 128;
    int tid = threadIdx.x, wid = tid >> 5, lane = tid & 31;
    int g = lane >> 2, tg = lane & 3;
    int wm = wid & 3, wn = wid >> 2;

    if (tid < 128) {
        int slot = m0 + tid;
        stok[tid] = ROUTED ? ((slot < cnt) ? g_perm[e * T_TOK + slot]
                                           : g_perm[e * T_TOK]) : slot;
    }
    __syncthreads();

    const __half* B1 = B1base + (ROUTED ? (size_t)e * F_DIM * H_DIM : 0);
    const __half* B2 = B2base + (ROUTED ? (size_t)e * F_DIM * H_DIM : 0);
    __half* outE = outBase + (ROUTED ? (size_t)e * T_TOK * nld : 0);
    uint32_t sbase = smem_u32(smem);

    uint32_t aOff = (uint32_t)((wm * 32 + (lane & 15)) * PITCH + (lane >> 4) * 16);
    uint32_t bOff = (uint32_t)((wn * 32 + (lane & 7) + (lane >> 4) * 8) * PITCH
                               + ((lane >> 3) & 1) * 16);

    // per stage: A rows [0,128), B1 [128,256), B2 [256,384); PITCH bytes/row
    #define ACT_LOAD(st, k0) {                                                  \
        uint32_t base = sbase + (st) * ACT_STAGE_B;                             \
        _Pragma("unroll")                                                       \
        for (int i = 0; i < 2; i++) {                                           \
            int id = tid + i * 512; int r = id >> 3, j = id & 7;                \
            cpa16s(base + r * PITCH + j * 16,                                   \
                   Ax + (size_t)stok[r] * KD + (k0) + j * 8);                   \
            size_t go = (size_t)(n0 + r) * KD + (k0) + j * 8;                   \
            cpa16s(base + (128 + r) * PITCH + j * 16, B1 + go);                 \
            cpa16s(base + (256 + r) * PITCH + j * 16, B2 + go);                 \
        }                                                                       \
        CP_COMMIT;                                                              \
    }

    float acc1[2][4][4], acc2[2][4][4];
    #pragma unroll
    for (int mt = 0; mt < 2; mt++)
        #pragma unroll
        for (int nt = 0; nt < 4; nt++)
            #pragma unroll
            for (int q = 0; q < 4; q++) { acc1[mt][nt][q] = 0.f; acc2[mt][nt][q] = 0.f; }

    const int NIT = KD / BK;   // 32
    ACT_LOAD(0, 0);
    ACT_LOAD(1, BK);

    for (int it = 0; it < NIT; ++it) {
        if (it + 1 < NIT) CP_WAIT(1); else CP_WAIT(0);
        __syncthreads();
        if (it + 2 < NIT) ACT_LOAD((it + 2) % STAGES, (it + 2) * BK);

        uint32_t stg = sbase + (it % STAGES) * ACT_STAGE_B;
        uint32_t aB = stg + aOff;
        uint32_t b1B = stg + 128 * PITCH + bOff;
        uint32_t b2B = stg + 256 * PITCH + bOff;

        #pragma unroll
        for (int s = 0; s < 4; s++) {   // four k16 steps
            uint32_t a[2][4];
            #pragma unroll
            for (int mt = 0; mt < 2; mt++)
                ldsm4(a[mt], aB + mt * (16 * PITCH) + s * 32);
            #pragma unroll
            for (int p = 0; p < 2; p++) {
                uint32_t rb1[4], rb2[4];
                ldsm4(rb1, b1B + p * (16 * PITCH) + s * 32);
                ldsm4(rb2, b2B + p * (16 * PITCH) + s * 32);
                #pragma unroll
                for (int mt = 0; mt < 2; mt++) {
                    mma16(acc1[mt][2 * p],     a[mt], rb1[0], rb1[1]);
                    mma16(acc1[mt][2 * p + 1], a[mt], rb1[2], rb1[3]);
                    mma16(acc2[mt][2 * p],     a[mt], rb2[0], rb2[1]);
                    mma16(acc2[mt][2 * p + 1], a[mt], rb2[2], rb2[3]);
                }
            }
        }
    }
    #undef ACT_LOAD

    #pragma unroll
    for (int mt = 0; mt < 2; mt++) {
        #pragma unroll
        for (int nt = 0; nt < 4; nt++) {
            float v[4];
            #pragma unroll
            for (int q = 0; q < 4; q++) {
                float gv = acc1[mt][nt][q], uv = acc2[mt][nt][q];
                v[q] = (gv / (1.f + __expf(-gv))) * uv;
            }
            __half2 lo = __floats2half2_rn(v[0], v[1]);
            __half2 hi = __floats2half2_rn(v[2], v[3]);
            int row = m0 + wm * 32 + mt * 16 + g;
            int col = n0 + wn * 32 + nt * 8 + tg * 2;
            *(uint32_t*)(outE + (size_t)row * nld + col)       = *(uint32_t*)&lo;
            *(uint32_t*)(outE + (size_t)(row + 8) * nld + col) = *(uint32_t*)&hi;
        }
    }
}

// ---------------------------------------------------------------------------
// down: C = A @ Wd (B pre-transposed [H][KD] k-contig). 512 threads, BK=64.
template <bool ROUTED>
__global__ void __launch_bounds__(512)
down_kernel(const __half* __restrict__ Abase,
            const __half* __restrict__ Bbase,
            float* __restrict__ out,
            int KD) {
    extern __shared__ __half smem[];

    int e = ROUTED ? blockIdx.z : 0;
    int cnt = ROUTED ? g_count[e] : T_TOK;
    int m0 = blockIdx.y * 128;
    if (m0 >= cnt) return;
    int n0 = blockIdx.x * 128;
    int tid = threadIdx.x, wid = tid >> 5, lane = tid & 31;
    int g = lane >> 2, tg = lane & 3;
    int wm = wid & 3, wn = wid >> 2;

    const __half* A = Abase + (ROUTED ? (size_t)e * T_TOK * KD : 0);
    const __half* B = Bbase + (ROUTED ? (size_t)e * H_DIM * KD : 0);
    float* outE = out + (ROUTED ? (size_t)e * T_TOK * H_DIM : 0);
    uint32_t sbase = smem_u32(smem);

    uint32_t aOff = (uint32_t)((wm * 32 + (lane & 15)) * PITCH + (lane >> 4) * 16);
    uint32_t bOff = (uint32_t)((wn * 32 + (lane & 7) + (lane >> 4) * 8) * PITCH
                               + ((lane >> 3) & 1) * 16);

    #define DOWN_LOAD(st, k0) {                                                 \
        uint32_t base = sbase + (st) * DOWN_STAGE_B;                            \
        _Pragma("unroll")                                                       \
        for (int i = 0; i < 2; i++) {                                           \
            int id = tid + i * 512; int r = id >> 3, j = id & 7;                \
            cpa16s(base + r * PITCH + j * 16,                                   \
                   A + (size_t)(m0 + r) * KD + (k0) + j * 8);                   \
            cpa16s(base + (128 + r) * PITCH + j * 16,                           \
                   B + (size_t)(n0 + r) * KD + (k0) + j * 8);                   \
        }                                                                       \
        CP_COMMIT;                                                              \
    }

    float acc[2][4][4];
    #pragma unroll
    for (int mt = 0; mt < 2; mt++)
        #pragma unroll
        for (int nt = 0; nt < 4; nt++)
            #pragma unroll
            for (int q = 0; q < 4; q++) acc[mt][nt][q] = 0.f;

    const int NIT = KD / BK;   // 22 or 44
    DOWN_LOAD(0, 0);
    DOWN_LOAD(1, BK);

    for (int it = 0; it < NIT; ++it) {
        if (it + 1 < NIT) CP_WAIT(1); else CP_WAIT(0);
        __syncthreads();
        if (it + 2 < NIT) DOWN_LOAD((it + 2) % STAGES, (it + 2) * BK);

        uint32_t stg = sbase + (it % STAGES) * DOWN_STAGE_B;
        uint32_t aB = stg + aOff;
        uint32_t bB = stg + 128 * PITCH + bOff;

        #pragma unroll
        for (int s = 0; s < 4; s++) {
            uint32_t a[2][4];
            #pragma unroll
            for (int mt = 0; mt < 2; mt++)
                ldsm4(a[mt], aB + mt * (16 * PITCH) + s * 32);
            #pragma unroll
            for (int p = 0; p < 2; p++) {
                uint32_t rb[4];
                ldsm4(rb, bB + p * (16 * PITCH) + s * 32);
                #pragma unroll
                for (int mt = 0; mt < 2; mt++) {
                    mma16(acc[mt][2 * p],     a[mt], rb[0], rb[1]);
                    mma16(acc[mt][2 * p + 1], a[mt], rb[2], rb[3]);
                }
            }
        }
    }
    #undef DOWN_LOAD

    #pragma unroll
    for (int mt = 0; mt < 2; mt++) {
        #pragma unroll
        for (int half = 0; half < 2; half++) {
            int rl = wm * 32 + mt * 16 + g + half * 8;
            float* dst = outE + (size_t)(m0 + rl) * H_DIM + n0;
            #pragma unroll
            for (int nt = 0; nt < 4; nt++) {
                int col = wn * 32 + nt * 8 + tg * 2;
                *(float2*)(dst + col) =
                    make_float2(acc[mt][nt][half * 2 + 0], acc[mt][nt][half * 2 + 1]);
            }
        }
    }
}

// ---------------------------------------------------------------------------
extern "C" void kernel_launch(void* const* d_in, const int* in_sizes, int n_in,
                              void* d_out, int out_size) {
    const float* x  = (const float*)d_in[0];
    const float* gw = (const float*)d_in[1];
    const float* gp = (const float*)d_in[2];
    const float* up = (const float*)d_in[3];
    const float* dp = (const float*)d_in[4];
    const float* sg = (const float*)d_in[5];
    const float* su = (const float*)d_in[6];
    const float* sd = (const float*)d_in[7];
    float* out = (float*)d_out;

    __half *xhP, *w1tP, *w2tP, *wdtP, *sgtP, *sutP, *sdtP, *acthP, *sacthP;
    float* doutP;
    cudaGetSymbolAddress((void**)&xhP,    g_xh);
    cudaGetSymbolAddress((void**)&w1tP,   g_w1t);
    cudaGetSymbolAddress((void**)&w2tP,   g_w2t);
    cudaGetSymbolAddress((void**)&wdtP,   g_wdt);
    cudaGetSymbolAddress((void**)&sgtP,   g_sgt);
    cudaGetSymbolAddress((void**)&sutP,   g_sut);
    cudaGetSymbolAddress((void**)&sdtP,   g_sdt);
    cudaGetSymbolAddress((void**)&acthP,  g_acth);
    cudaGetSymbolAddress((void**)&sacthP, g_sacth);
    cudaGetSymbolAddress((void**)&doutP,  g_dout);

    cudaFuncSetAttribute(act_kernel<true>,   cudaFuncAttributeMaxDynamicSharedMemorySize, ACT_SMEM);
    cudaFuncSetAttribute(act_kernel<false>,  cudaFuncAttributeMaxDynamicSharedMemorySize, ACT_SMEM);
    cudaFuncSetAttribute(down_kernel<true>,  cudaFuncAttributeMaxDynamicSharedMemorySize, DOWN_SMEM);
    cudaFuncSetAttribute(down_kernel<false>, cudaFuncAttributeMaxDynamicSharedMemorySize, DOWN_SMEM);

    // one-time side streams + events (created outside graph capture)
    static cudaStream_t s1 = nullptr, s2 = nullptr;
    static cudaEvent_t evRoot = nullptr, evFork = nullptr, evJoin = nullptr,
                       evDp = nullptr, evSu = nullptr, evSd = nullptr;
    if (s1 == nullptr) {
        cudaStreamCreateWithFlags(&s1, cudaStreamNonBlocking);
        cudaStreamCreateWithFlags(&s2, cudaStreamNonBlocking);
        cudaEventCreateWithFlags(&evRoot, cudaEventDisableTiming);
        cudaEventCreateWithFlags(&evFork, cudaEventDisableTiming);
        cudaEventCreateWithFlags(&evJoin, cudaEventDisableTiming);
        cudaEventCreateWithFlags(&evDp,   cudaEventDisableTiming);
        cudaEventCreateWithFlags(&evSu,   cudaEventDisableTiming);
        cudaEventCreateWithFlags(&evSd,   cudaEventDisableTiming);
    }

    dim3 tb(32, 8);

    // s0: root (side streams must join capture via an event recorded here)
    zero_counts_kernel<<<1, 32>>>();
    cudaEventRecord(evRoot, 0);

    // s0: gating (also produces xh) — runs concurrent with transposes below
    gate_topk_kernel<<<T_TOK, 256>>>(x, gw);
    cudaEventRecord(evFork, 0);

    // s1: join capture, then gate/up weight transposes (independent of gate)
    cudaStreamWaitEvent(s1, evRoot, 0);
    transpose_f2h_kernel<<<dim3(F_DIM / 32, H_DIM / 64, N_EXP), tb, 0, s1>>>(gp, w1tP, H_DIM, F_DIM);
    transpose_f2h_kernel<<<dim3(F_DIM / 32, H_DIM / 64, N_EXP), tb, 0, s1>>>(up, w2tP, H_DIM, F_DIM);

    // s2: join capture, then dp + shared weight transposes (independent of gate)
    cudaStreamWaitEvent(s2, evRoot, 0);
    transpose_f2h_kernel<<<dim3(H_DIM / 32, F_DIM / 64, N_EXP), tb, 0, s2>>>(dp, wdtP, F_DIM, H_DIM);
    cudaEventRecord(evDp, s2);
    transpose_f2h_kernel<<<dim3(SF_DIM / 32, H_DIM / 64, 1), tb, 0, s2>>>(sg, sgtP, H_DIM, SF_DIM);
    transpose_f2h_kernel<<<dim3(SF_DIM / 32, H_DIM / 64, 1), tb, 0, s2>>>(su, sutP, H_DIM, SF_DIM);
    cudaEventRecord(evSu, s2);
    transpose_f2h_kernel<<<dim3(H_DIM / 32, SF_DIM / 64, 1), tb, 0, s2>>>(sd, sdtP, SF_DIM, H_DIM);
    cudaEventRecord(evSd, s2);

    // s1: routed chain (act needs gate + xh; down needs dp transpose)
    cudaStreamWaitEvent(s1, evFork, 0);
    act_kernel<true><<<dim3(F_DIM / 128, T_TOK / 128, N_EXP), 512, ACT_SMEM, s1>>>(xhP, w1tP, w2tP, acthP, F_DIM);
    cudaStreamWaitEvent(s1, evDp, 0);
    down_kernel<true><<<dim3(H_DIM / 128, T_TOK / 128, N_EXP), 512, DOWN_SMEM, s1>>>(acthP, wdtP, doutP, F_DIM);
    cudaEventRecord(evJoin, s1);

    // s0: shared chain (act needs sg/su + xh from gate on this stream)
    cudaStreamWaitEvent(0, evSu, 0);
    act_kernel<false><<<dim3(SF_DIM / 128, T_TOK / 128, 1), 512, ACT_SMEM>>>(xhP, sgtP, sutP, sacthP, SF_DIM);
    cudaStreamWaitEvent(0, evSd, 0);
    down_kernel<false><<<dim3(H_DIM / 128, T_TOK / 128, 1), 512, DOWN_SMEM>>>(sacthP, sdtP, out, SF_DIM);

    // join: combine needs both chains
    cudaStreamWaitEvent(0, evJoin, 0);
    combine_kernel<<<T_TOK, 256>>>(out);
}